// round 10
// baseline (speedup 1.0000x reference)
#include <cuda_runtime.h>

#define NPTS 16384
#define CC 16
#define HH 256
#define WW 704
#define HWIMG (HH*WW)        // 180224
#define EPSBN 1e-3f
#define NBB 128              // persistent blocks (<=148 SMs -> co-resident)
#define NT 512               // threads/block (4 threads per point)
#define NW 16                // warps/block
#define PPB 128              // points per block
#define INVN (1.0f/16384.0f)
#define NSX 44               // supercells per row (704/16)
#define NSC (HH*NSX)         // 11264 = 128*88
#define CHUNK 88
#define KNNR 10
#define KNNTH 120ULL
#define FULLM 0xffffffffu

// ------------------------- device scratch ----------------------------------
__device__ __align__(16) float g_val[HWIMG*CC];
__device__ __align__(16) float g_imt[HWIMG*CC];
__device__ __align__(16) float g_neigh[NPTS*CC];
__device__ __align__(16) float g_pts[NPTS*CC];
__device__ __align__(16) float g_Y3[NPTS*CC];
__device__ float g_pA[34*NBB];       // transposed: [item][block]
__device__ float g_p2[37*NBB];
__device__ float g_p3[32*NBB];
__device__ int g_cellCnt[NSC];       // zero-init; self-zeroing (scatter drains)
__device__ int g_cellStart[NSC+1];
__device__ int g_bs[NBB];
__device__ unsigned g_packed[NPTS];  // (idx<<18)|(y<<10)|x, grouped by supercell
__device__ int g_bc[4];              // phase barrier counters (self-resetting)

__device__ __forceinline__ float warpSum(float v){
#pragma unroll
  for(int o=16;o>0;o>>=1) v += __shfl_down_sync(FULLM, v, o);
  return v;
}
__device__ __forceinline__ int warpSumI(int v){
#pragma unroll
  for(int o=16;o>0;o>>=1) v += __shfl_down_sync(FULLM, v, o);
  return v;
}
__device__ __forceinline__ float warpMax(float v){
#pragma unroll
  for(int o=16;o>0;o>>=1) v = fmaxf(v, __shfl_down_sync(FULLM, v, o));
  return v;
}

// grid barrier across NBB resident blocks
__device__ __forceinline__ void gbar(int idx){
  __syncthreads();
  if(threadIdx.x==0){
    __threadfence();
    atomicAdd(&g_bc[idx], 1);
    while(((volatile int*)g_bc)[idx] < NBB) __nanosleep(32);
    __threadfence();
  }
  __syncthreads();
}

// ------------------------- K1: persistent init + A + scan + scatter + C -----
__global__ void __launch_bounds__(NT) k_SS(const float* __restrict__ pf,
    const int* __restrict__ grid,
    const float* __restrict__ Wk, const float* __restrict__ bk,
    const float* __restrict__ gk, const float* __restrict__ betak,
    const float* __restrict__ Wt, const float* __restrict__ bt,
    const float* __restrict__ imf,
    const float* __restrict__ Wval, const float* __restrict__ bval){
  __shared__ float sW[CC*CC], sWv[CC*CC];
  __shared__ float sb[CC], sbv[CC];
  __shared__ float red[NW][37];
  __shared__ int sredI[NW];
  __shared__ float sA[34];
  __shared__ float sa1[CC], sb1[CC], scc[2];
  int b=blockIdx.x, t=threadIdx.x;
  int lane=t&31, w=t>>5, r=t&3;
  int gbase = (lane&~3);
  if(b==0 && t==0) *(volatile int*)&g_bc[3] = 0;

  for(int i=t;i<CC*CC;i+=NT){ sW[i]=Wk[i]; sWv[i]=Wval[i]; }
  if(t<CC){ sb[t]=bk[t]; sbv[t]=bval[t]; }
  __syncthreads();

  // ---- init: value table + imf transpose (strided over whole image) ----
  for(int p = b*NT+t; p < HWIMG; p += NBB*NT){
    float x[CC];
#pragma unroll
    for(int c=0;c<CC;c++) x[c] = imf[c*HWIMG + p];
    float4* it = (float4*)(g_imt + p*CC);
    it[0]=make_float4(x[0],x[1],x[2],x[3]);
    it[1]=make_float4(x[4],x[5],x[6],x[7]);
    it[2]=make_float4(x[8],x[9],x[10],x[11]);
    it[3]=make_float4(x[12],x[13],x[14],x[15]);
    float o[CC];
#pragma unroll
    for(int j=0;j<CC;j++){
      float s=sbv[j];
#pragma unroll
      for(int c=0;c<CC;c++) s += x[c]*sWv[c*CC+j];
      o[j]=s;
    }
    float4* dst = (float4*)(g_val + p*CC);
    dst[0]=make_float4(o[0],o[1],o[2],o[3]);
    dst[1]=make_float4(o[4],o[5],o[6],o[7]);
    dst[2]=make_float4(o[8],o[9],o[10],o[11]);
    dst[3]=make_float4(o[12],o[13],o[14],o[15]);
  }

  // ---- P0: count + Y1 (4 threads/point; thread owns channels 4r..4r+3) ----
  int n = b*PPB + (t>>2);
  int gyi = grid[2*n], gxi = grid[2*n+1];
  if(r==0) atomicAdd(&g_cellCnt[gyi*NSX + (gxi>>4)], 1);
  float x4[4];
  { float4 xv = *(const float4*)(pf + n*CC + 4*r);
    x4[0]=xv.x; x4[1]=xv.y; x4[2]=xv.z; x4[3]=xv.w; }
  float y4v[4];
#pragma unroll
  for(int j=0;j<4;j++) y4v[j]=sb[4*r+j];
#pragma unroll
  for(int rr=0;rr<4;rr++){
    float xs[4];
#pragma unroll
    for(int k=0;k<4;k++) xs[k]=__shfl_sync(FULLM, x4[k], gbase+rr);
#pragma unroll
    for(int k=0;k<4;k++)
#pragma unroll
      for(int j=0;j<4;j++) y4v[j] += xs[k]*sW[(4*rr+k)*CC + 4*r+j];
  }
  {
    float s1[4], s2[4];
#pragma unroll
    for(int j=0;j<4;j++){ s1[j]=y4v[j]; s2[j]=y4v[j]*y4v[j]; }
#pragma unroll
    for(int o=4;o<32;o<<=1)
#pragma unroll
      for(int j=0;j<4;j++){
        s1[j]+=__shfl_down_sync(FULLM,s1[j],o);
        s2[j]+=__shfl_down_sync(FULLM,s2[j],o);
      }
    if(lane<4)
#pragma unroll
      for(int j=0;j<4;j++){ red[w][4*lane+j]=s1[j]; red[w][16+4*lane+j]=s2[j]; }
    float gy=(r==0)?(float)gyi:0.f, gx=(r==0)?(float)gxi:0.f;
    float sgy=warpSum(gy), sgx=warpSum(gx);
    if(!lane){ red[w][32]=sgy; red[w][33]=sgx; }
  }
  __syncthreads();
  if(t<34){
    float s=0.f;
#pragma unroll
    for(int k=0;k<NW;k++) s += red[k][t];
    g_pA[t*NBB+b] = s;
  }
  gbar(0);

  // ---- P1: warp-0 scan of this block's 88 supercell counts ----
  int cbase = b*CHUNK;
  if(w==0){
    int base3 = lane*3;
    int loc[3]; int s=0;
#pragma unroll
    for(int i=0;i<3;i++){
      loc[i]=s;
      int idx=base3+i;
      if(idx<CHUNK) s += g_cellCnt[cbase+idx];
    }
    int incl=s;
#pragma unroll
    for(int o=1;o<32;o<<=1){ int xx=__shfl_up_sync(FULLM,incl,o); if(lane>=o) incl+=xx; }
    int pref = incl - s;
#pragma unroll
    for(int i=0;i<3;i++){
      int idx=base3+i;
      if(idx<CHUNK) g_cellStart[cbase+idx] = pref + loc[i];
    }
    if(lane==31) g_bs[b] = incl;
  }
  gbar(1);

  // ---- P2: add block offsets ----
  {
    int vb = (t<b) ? g_bs[t] : 0;
    int s = warpSumI(vb);
    if(!lane) sredI[w]=s;
    __syncthreads();
    int off=0;
#pragma unroll
    for(int k=0;k<NW;k++) off += sredI[k];
    if(t<CHUNK) g_cellStart[cbase+t] += off;
    if(b==0 && t==0) g_cellStart[NSC]=NPTS;
  }
  gbar(2);

  // ---- P3: stats finalize + scatter + pts/Y3 + p2 partials ----
  for(int i=w;i<34;i+=NW){
    const float* pp = g_pA + i*NBB;
    float s = pp[lane]+pp[lane+32]+pp[lane+64]+pp[lane+96];
    s = warpSum(s);
    if(!lane) sA[i]=s;
  }
  for(int i=t;i<CC*CC;i+=NT) sW[i]=Wt[i];
  if(t<CC) sb[t]=bt[t];
  __syncthreads();
  if(t<CC){
    float m = sA[t]*INVN;
    float vv = sA[16+t]*INVN - m*m;
    float is = rsqrtf(vv+EPSBN);
    sa1[t] = is*gk[t];
    sb1[t] = betak[t] - m*is*gk[t];
  }
  if(t==16) scc[0]=sA[32]*INVN;
  if(t==17) scc[1]=sA[33]*INVN;
  __syncthreads();
  if(r==0){
    int cid = gyi*NSX + (gxi>>4);
    int old = atomicSub(&g_cellCnt[cid], 1);   // drains to 0 (replay-safe)
    g_packed[g_cellStart[cid] + old - 1] =
        ((unsigned)n<<18) | ((unsigned)gyi<<10) | (unsigned)gxi;
  }
  float p4[4];
#pragma unroll
  for(int j=0;j<4;j++) p4[j] = y4v[j]*sa1[4*r+j] + sb1[4*r+j];
  *(float4*)(g_pts + n*CC + 4*r) = make_float4(p4[0],p4[1],p4[2],p4[3]);
  float y3[4];
#pragma unroll
  for(int j=0;j<4;j++) y3[j]=sb[4*r+j];
#pragma unroll
  for(int rr=0;rr<4;rr++){
    float xs[4];
#pragma unroll
    for(int k=0;k<4;k++) xs[k]=__shfl_sync(FULLM, p4[k], gbase+rr);
#pragma unroll
    for(int k=0;k<4;k++)
#pragma unroll
      for(int j=0;j<4;j++) y3[j] += xs[k]*sW[(4*rr+k)*CC + 4*r+j];
  }
  *(float4*)(g_Y3 + n*CC + 4*r) = make_float4(y3[0],y3[1],y3[2],y3[3]);
  {
    float s1[4], s2[4];
#pragma unroll
    for(int j=0;j<4;j++){ s1[j]=y3[j]; s2[j]=y3[j]*y3[j]; }
#pragma unroll
    for(int o=4;o<32;o<<=1)
#pragma unroll
      for(int j=0;j<4;j++){
        s1[j]+=__shfl_down_sync(FULLM,s1[j],o);
        s2[j]+=__shfl_down_sync(FULLM,s2[j],o);
      }
    if(lane<4)
#pragma unroll
      for(int j=0;j<4;j++){ red[w][4*lane+j]=s1[j]; red[w][16+4*lane+j]=s2[j]; }
    float ry=(float)gyi-scc[0], rx=(float)gxi-scc[1];
    float vyy=(r==0)?ry*ry:0.f, vxx=(r==0)?rx*rx:0.f, vxy=(r==0)?ry*rx:0.f;
    float myy=(r==0)?fabsf(ry):0.f, mxx2=(r==0)?fabsf(rx):0.f;
    float a_=warpSum(vyy); if(!lane) red[w][32]=a_;
    float b_=warpSum(vxx); if(!lane) red[w][33]=b_;
    float c_=warpSum(vxy); if(!lane) red[w][34]=c_;
    float d_=warpMax(myy); if(!lane) red[w][35]=d_;
    float e_=warpMax(mxx2); if(!lane) red[w][36]=e_;
  }
  __syncthreads();
  if(t<35){
    float s=0.f;
#pragma unroll
    for(int k=0;k<NW;k++) s += red[k][t];
    g_p2[t*NBB+b]=s;
  } else if(t<37){
    float m=0.f;
#pragma unroll
    for(int k=0;k<NW;k++) m = fmaxf(m, red[k][t]);
    g_p2[t*NBB+b]=m;
  }
}

// ------------------------- KNN helpers --------------------------------------
__device__ __forceinline__ unsigned long long umin64(unsigned long long a, unsigned long long b){
  return a<b ? a : b;
}
__device__ __forceinline__ unsigned long long umax64(unsigned long long a, unsigned long long b){
  return a<b ? b : a;
}
#define INS9(L0,L1,L2,L3,L4,L5,L6,L7,L8,KEY) do{ \
  unsigned long long _k=(KEY); \
  if(_k < L8){ \
    unsigned long long _t; \
    _t=L0; L0=umin64(_t,_k); _k=umax64(_t,_k); \
    _t=L1; L1=umin64(_t,_k); _k=umax64(_t,_k); \
    _t=L2; L2=umin64(_t,_k); _k=umax64(_t,_k); \
    _t=L3; L3=umin64(_t,_k); _k=umax64(_t,_k); \
    _t=L4; L4=umin64(_t,_k); _k=umax64(_t,_k); \
    _t=L5; L5=umin64(_t,_k); _k=umax64(_t,_k); \
    _t=L6; L6=umin64(_t,_k); _k=umax64(_t,_k); \
    _t=L7; L7=umin64(_t,_k); _k=umax64(_t,_k); \
    L8=umin64(L8,_k); \
  } }while(0)

__device__ __forceinline__ int isqrt_dev(int v){
  if(v < 0) return -1;
  int h = (int)sqrtf((float)v);
  while((h+1)*(h+1) <= v) h++;
  while(h>0 && h*h > v) h--;
  return h;
}

__device__ __forceinline__ unsigned long long mkkey(unsigned p, int qy, int qx){
  int dy = (int)((p>>10)&0xFFu) - qy;
  int dx = (int)(p&0x3FFu) - qx;
  return ((unsigned long long)(unsigned)(dy*dy+dx*dx) << 32) | p;
}

// ------------------------- K2: warp-per-query KNN + neighbor mean -----------
__global__ void __launch_bounds__(128) k_knn(const int* __restrict__ grid){
  int lane = threadIdx.x & 31;
  int n = blockIdx.x*4 + (threadIdx.x >> 5);
  int qy = __ldg(&grid[2*n]), qx = __ldg(&grid[2*n+1]);

  unsigned long long l0=~0ULL,l1=~0ULL,l2=~0ULL,l3=~0ULL,l4=~0ULL,
                     l5=~0ULL,l6=~0ULL,l7=~0ULL,l8=~0ULL;
  int row = qy - KNNR + lane;
  int s=0, e=0;
  if(lane < 2*KNNR+1 && row >= 0 && row < HH){
    int sxlo = max(qx-KNNR,0) >> 4;
    int sxhi = min(qx+KNNR,WW-1) >> 4;
    s = g_cellStart[row*NSX + sxlo];
    e = g_cellStart[row*NSX + sxhi + 1];
  }
  while(__any_sync(FULLM, s<e)){
    if(s<e){
      unsigned p = g_packed[s]; s++;
      unsigned long long key = mkkey(p, qy, qx);
      INS9(l0,l1,l2,l3,l4,l5,l6,l7,l8,key);
    }
  }
  unsigned long long w0,w1,w2,w3,w4,w5,w6,w7,w8;
#define ROUND(WR) { \
    unsigned long long m=l0; \
    _Pragma("unroll") \
    for(int o=16;o>0;o>>=1){ unsigned long long t2=__shfl_xor_sync(FULLM,m,o); if(t2<m)m=t2; } \
    WR = m; \
    if(l0==m){ l0=l1;l1=l2;l2=l3;l3=l4;l4=l5;l5=l6;l6=l7;l7=l8;l8=~0ULL; } }
  ROUND(w0) ROUND(w1) ROUND(w2) ROUND(w3) ROUND(w4)
  ROUND(w5) ROUND(w6) ROUND(w7) ROUND(w8)
#undef ROUND

  if(w8 == ~0ULL || (w8>>32) > KNNTH){
    unsigned long long f0=~0ULL,f1=~0ULL,f2=~0ULL,f3=~0ULL,f4=~0ULL,
                       f5=~0ULL,f6=~0ULL,f7=~0ULL,f8=~0ULL;
    if(lane==0){
      for(int d=0; d<HH; d++){
        if(f8 != ~0ULL && (unsigned long long)(d*d) > (f8>>32)) break;
        for(int sgn=0; sgn<2; sgn++){
          if(d==0 && sgn) break;
          int yy = sgn ? qy+d : qy-d;
          if((unsigned)yy >= HH) continue;
          int xlo=0, xhi=WW-1;
          if(f8 != ~0ULL){
            int vv = (int)(f8>>32) - d*d;
            if(vv < 0) continue;
            int hw = isqrt_dev(vv);
            xlo = max(qx-hw,0); xhi = min(qx+hw,WW-1);
          }
          int ss = g_cellStart[yy*NSX + (xlo>>4)];
          int ee = g_cellStart[yy*NSX + (xhi>>4) + 1];
          for(; ss<ee; ss++){
            unsigned long long key = mkkey(g_packed[ss], qy, qx);
            INS9(f0,f1,f2,f3,f4,f5,f6,f7,f8,key);
          }
        }
      }
    }
    w1=__shfl_sync(FULLM,f1,0); w2=__shfl_sync(FULLM,f2,0);
    w3=__shfl_sync(FULLM,f3,0); w4=__shfl_sync(FULLM,f4,0); w5=__shfl_sync(FULLM,f5,0);
    w6=__shfl_sync(FULLM,f6,0); w7=__shfl_sync(FULLM,f7,0); w8=__shfl_sync(FULLM,f8,0);
  }

  unsigned p1=(unsigned)w1, p2=(unsigned)w2, p3=(unsigned)w3, p4=(unsigned)w4,
           p5=(unsigned)w5, p6=(unsigned)w6, p7=(unsigned)w7, p8=(unsigned)w8;
#define POS(P) ((int)(((P)>>10)&0xFFu)*WW + (int)((P)&0x3FFu))
  int o1=POS(p1),o2=POS(p2),o3=POS(p3),o4=POS(p4),
      o5=POS(p5),o6=POS(p6),o7=POS(p7),o8=POS(p8);
#undef POS
  int ni = lane>>2;
  int off = o1;
  off = (ni==1)?o2:off; off = (ni==2)?o3:off; off = (ni==3)?o4:off;
  off = (ni==4)?o5:off; off = (ni==5)?o6:off; off = (ni==6)?o7:off;
  off = (ni==7)?o8:off;
  float4 v = *(const float4*)(g_imt + off*CC + (lane&3)*4);
#pragma unroll
  for(int o=4;o<=16;o<<=1){
    v.x += __shfl_xor_sync(FULLM, v.x, o);
    v.y += __shfl_xor_sync(FULLM, v.y, o);
    v.z += __shfl_xor_sync(FULLM, v.z, o);
    v.w += __shfl_xor_sync(FULLM, v.w, o);
  }
  if(lane < 4){
    v.x*=0.125f; v.y*=0.125f; v.z*=0.125f; v.w*=0.125f;
    ((float4*)(g_neigh + n*CC))[lane] = v;
  }
}

// ------------------------- K3: deform attn + fuse + final BN (4 thr/point) --
__global__ void __launch_bounds__(NT) k_EG(const int* __restrict__ grid,
    const float* __restrict__ Wfc, const float* __restrict__ gfc, const float* __restrict__ betafc,
    const float* __restrict__ gt,  const float* __restrict__ betat,
    const float* __restrict__ Woff,const float* __restrict__ boff,
    const float* __restrict__ Wattn,const float* __restrict__ battn,
    const float* __restrict__ Wout,const float* __restrict__ bout,
    const float* __restrict__ Wf,  const float* __restrict__ bf,
    const float* __restrict__ gf,  const float* __restrict__ betaf,
    float* __restrict__ out){
  __shared__ float sF[40];
  __shared__ float sWoff[CC*32], sWattn[CC*16], sWout[CC*16], sWf[32*CC];
  __shared__ float sboff[32], sbattn[16], sbout[16], sbf[16];
  __shared__ float sa3[16], sb3[16], su0[16], su1[16], sb2[16], sc[2];
  __shared__ float red[NW][32];
  __shared__ float sP[32], a4[16], b4[16];
  int b=blockIdx.x, t=threadIdx.x;
  int lane=t&31, w=t>>5, r=t&3;
  int gbase = (lane&~3);
  if(b==0 && t==0){
    *(volatile int*)&g_bc[0]=0;
    *(volatile int*)&g_bc[1]=0;
    *(volatile int*)&g_bc[2]=0;
  }
  for(int i=t;i<CC*32;i+=NT) sWoff[i]=Woff[i];
  for(int i=t;i<CC*16;i+=NT){ sWattn[i]=Wattn[i]; sWout[i]=Wout[i]; }
  for(int i=t;i<32*CC;i+=NT) sWf[i]=Wf[i];
  if(t<32) sboff[t]=boff[t];
  if(t<16){ sbattn[t]=battn[t]; sbout[t]=bout[t]; sbf[t]=bf[t]; }
  // reduce partials (16 warps cover items 0..34; warps 0-3 handle extras)
  for(int i=w;i<35;i+=NW){
    const float* pp = g_p2 + i*NBB;
    float s = pp[lane]+pp[lane+32]+pp[lane+64]+pp[lane+96];
    s = warpSum(s);
    if(!lane) sF[i]=s;
  }
  if(w==4){
    const float* pp = g_p2 + 35*NBB;
    float m = fmaxf(fmaxf(pp[lane],pp[lane+32]),fmaxf(pp[lane+64],pp[lane+96]));
    m = warpMax(m);
    if(!lane) sF[35]=m;
  } else if(w==5){
    const float* pp = g_p2 + 36*NBB;
    float m = fmaxf(fmaxf(pp[lane],pp[lane+32]),fmaxf(pp[lane+64],pp[lane+96]));
    m = warpMax(m);
    if(!lane) sF[36]=m;
  } else if(w==6){
    const float* pp = g_pA + 32*NBB;
    float s = pp[lane]+pp[lane+32]+pp[lane+64]+pp[lane+96];
    s = warpSum(s);
    if(!lane) sF[37]=s;
  } else if(w==7){
    const float* pp = g_pA + 33*NBB;
    float s = pp[lane]+pp[lane+32]+pp[lane+64]+pp[lane+96];
    s = warpSum(s);
    if(!lane) sF[38]=s;
  }
  __syncthreads();
  if(t<16){
    float m3 = sF[t]*INVN;
    float v3 = sF[16+t]*INVN - m3*m3;
    float is3 = rsqrtf(v3+EPSBN);
    sa3[t] = is3*gt[t];
    sb3[t] = betat[t] - m3*is3*gt[t];
    float mxy = sF[35]; if(mxy==0.f) mxy=1.f;
    float mxx = sF[36]; if(mxx==0.f) mxx=1.f;
    float Syy=sF[32]*INVN, Sxx=sF[33]*INVN, Sxy=sF[34]*INVN;
    float w0 = Wfc[t]/mxy;
    float w1 = Wfc[16+t]/mxx;
    float v2 = w0*w0*Syy + 2.f*w0*w1*Sxy + w1*w1*Sxx;
    float a2 = rsqrtf(v2+EPSBN)*gfc[t];
    su0[t]=w0*a2; su1[t]=w1*a2; sb2[t]=betafc[t];
  }
  if(t==16){ sc[0]=sF[37]*INVN; sc[1]=sF[38]*INVN; }
  __syncthreads();

  int n = b*PPB + (t>>2);
  int qyi = grid[2*n], qxi = grid[2*n+1];
  float gy=(float)qyi, gx=(float)qxi;
  float ry=gy-sc[0], rx=gx-sc[1];
  float q4[4];
  { float4 pv = *(const float4*)(g_pts + n*CC + 4*r);
    q4[0]=pv.x+ry*su0[4*r+0]+rx*su1[4*r+0]+sb2[4*r+0];
    q4[1]=pv.y+ry*su0[4*r+1]+rx*su1[4*r+1]+sb2[4*r+1];
    q4[2]=pv.z+ry*su0[4*r+2]+rx*su1[4*r+2]+sb2[4*r+2];
    q4[3]=pv.w+ry*su0[4*r+3]+rx*su1[4*r+3]+sb2[4*r+3]; }

  // thread r owns head r: 4 logits + 8 offsets
  float lg[4], offy[4], offx[4];
#pragma unroll
  for(int p=0;p<4;p++){
    lg[p]=sbattn[4*r+p];
    offy[p]=sboff[r*8+p*2];
    offx[p]=sboff[r*8+p*2+1];
  }
#pragma unroll
  for(int rr=0;rr<4;rr++){
    float qs[4];
#pragma unroll
    for(int k=0;k<4;k++) qs[k]=__shfl_sync(FULLM, q4[k], gbase+rr);
#pragma unroll
    for(int k=0;k<4;k++){
      int c = 4*rr+k;
#pragma unroll
      for(int p=0;p<4;p++){
        lg[p]  += qs[k]*sWattn[c*16 + 4*r + p];
        offy[p]+= qs[k]*sWoff[c*32 + r*8 + p*2];
        offx[p]+= qs[k]*sWoff[c*32 + r*8 + p*2+1];
      }
    }
  }
  float mx=fmaxf(fmaxf(lg[0],lg[1]),fmaxf(lg[2],lg[3]));
  float e0=expf(lg[0]-mx), e1=expf(lg[1]-mx), e2=expf(lg[2]-mx), e3=expf(lg[3]-mx);
  float inv=1.f/(e0+e1+e2+e3);
  lg[0]=e0*inv; lg[1]=e1*inv; lg[2]=e2*inv; lg[3]=e3*inv;

  float acc4[4]={0.f,0.f,0.f,0.f};
#define CORNER(Yf,Xf,Wgt) do{ \
    float _y=(Yf), _x=(Xf); \
    if(_y>=0.f && _y<=(float)(HH-1) && _x>=0.f && _x<=(float)(WW-1)){ \
      int _i = ((int)_y)*WW + (int)_x; \
      const float4 _v = *(const float4*)(g_val + _i*CC + 4*r); \
      float _w=(Wgt); \
      acc4[0]+=_w*_v.x; acc4[1]+=_w*_v.y; acc4[2]+=_w*_v.z; acc4[3]+=_w*_v.w; \
    } }while(0)
#pragma unroll
  for(int p=0;p<4;p++){
    float ly=gy+offy[p], lx=gx+offx[p];
    float fy=floorf(ly), fx=floorf(lx);
    float wy=ly-fy, wx=lx-fx;
    float ap=lg[p];
    CORNER(fy,     fx,     ap*(1.f-wy)*(1.f-wx));
    CORNER(fy,     fx+1.f, ap*(1.f-wy)*wx);
    CORNER(fy+1.f, fx,     ap*wy*(1.f-wx));
    CORNER(fy+1.f, fx+1.f, ap*wy*wx);
  }
#undef CORNER

  float img4[4];
#pragma unroll
  for(int j=0;j<4;j++) img4[j]=sbout[4*r+j];
#pragma unroll
  for(int rr=0;rr<4;rr++){
    float as[4];
#pragma unroll
    for(int k=0;k<4;k++) as[k]=__shfl_sync(FULLM, acc4[k], gbase+rr);
#pragma unroll
    for(int k=0;k<4;k++)
#pragma unroll
      for(int j=0;j<4;j++) img4[j] += as[k]*sWout[(4*rr+k)*16 + 4*r+j];
  }
  { float4 nb = *(const float4*)(g_neigh + n*CC + 4*r);
    img4[0]+=nb.x; img4[1]+=nb.y; img4[2]+=nb.z; img4[3]+=nb.w; }

  float pp4[4];
  { float4 yv = *(const float4*)(g_Y3 + n*CC + 4*r);
    pp4[0]=yv.x*sa3[4*r+0]+sb3[4*r+0];
    pp4[1]=yv.y*sa3[4*r+1]+sb3[4*r+1];
    pp4[2]=yv.z*sa3[4*r+2]+sb3[4*r+2];
    pp4[3]=yv.w*sa3[4*r+3]+sb3[4*r+3]; }

  float y4f[4];
#pragma unroll
  for(int j=0;j<4;j++) y4f[j]=sbf[4*r+j];
#pragma unroll
  for(int rr=0;rr<4;rr++){
    float ps[4], is_[4];
#pragma unroll
    for(int k=0;k<4;k++){
      ps[k] =__shfl_sync(FULLM, pp4[k],  gbase+rr);
      is_[k]=__shfl_sync(FULLM, img4[k], gbase+rr);
    }
#pragma unroll
    for(int k=0;k<4;k++){
      float pv=fmaxf(ps[k],0.f), iv=fmaxf(is_[k],0.f);
#pragma unroll
      for(int j=0;j<4;j++)
        y4f[j] += pv*sWf[(4*rr+k)*16 + 4*r+j] + iv*sWf[(16+4*rr+k)*16 + 4*r+j];
    }
  }
  {
    float s1[4], s2[4];
#pragma unroll
    for(int j=0;j<4;j++){ s1[j]=y4f[j]; s2[j]=y4f[j]*y4f[j]; }
#pragma unroll
    for(int o=4;o<32;o<<=1)
#pragma unroll
      for(int j=0;j<4;j++){
        s1[j]+=__shfl_down_sync(FULLM,s1[j],o);
        s2[j]+=__shfl_down_sync(FULLM,s2[j],o);
      }
    if(lane<4)
#pragma unroll
      for(int j=0;j<4;j++){ red[w][4*lane+j]=s1[j]; red[w][16+4*lane+j]=s2[j]; }
  }
  __syncthreads();
  if(t<32){
    float s=0.f;
#pragma unroll
    for(int k=0;k<NW;k++) s += red[k][t];
    g_p3[t*NBB+b]=s;
  }

  gbar(3);

  // ---- final BN + relu (y4f still in registers) ----
  for(int i=w;i<32;i+=NW){
    const float* pp = g_p3 + i*NBB;
    float s = pp[lane]+pp[lane+32]+pp[lane+64]+pp[lane+96];
    s = warpSum(s);
    if(!lane) sP[i]=s;
  }
  __syncthreads();
  if(t<16){
    float m = sP[t]*INVN;
    float vv = sP[16+t]*INVN - m*m;
    float is = rsqrtf(vv+EPSBN);
    a4[t]=is*gf[t];
    b4[t]=betaf[t] - m*is*gf[t];
  }
  __syncthreads();
  float4 ov;
  ov.x = fmaxf(y4f[0]*a4[4*r+0]+b4[4*r+0], 0.f);
  ov.y = fmaxf(y4f[1]*a4[4*r+1]+b4[4*r+1], 0.f);
  ov.z = fmaxf(y4f[2]*a4[4*r+2]+b4[4*r+2], 0.f);
  ov.w = fmaxf(y4f[3]*a4[4*r+3]+b4[4*r+3], 0.f);
  *(float4*)(out + n*CC + 4*r) = ov;
}

// ------------------------- launch ------------------------------------------
extern "C" void kernel_launch(void* const* d_in, const int* in_sizes, int n_in,
                              void* d_out, int out_size){
  const float* pf     = (const float*)d_in[0];
  const float* imf    = (const float*)d_in[1];
  const int*   grid   = (const int*)  d_in[2];
  const float* Wk     = (const float*)d_in[3];
  const float* bk     = (const float*)d_in[4];
  const float* gk     = (const float*)d_in[5];
  const float* betak  = (const float*)d_in[6];
  const float* Wfc    = (const float*)d_in[7];
  /* bfc = d_in[8] cancels analytically */
  const float* gfc    = (const float*)d_in[9];
  const float* betafc = (const float*)d_in[10];
  const float* Wt     = (const float*)d_in[11];
  const float* bt     = (const float*)d_in[12];
  const float* gt     = (const float*)d_in[13];
  const float* betat  = (const float*)d_in[14];
  const float* Woff   = (const float*)d_in[15];
  const float* boff   = (const float*)d_in[16];
  const float* Wattn  = (const float*)d_in[17];
  const float* battn  = (const float*)d_in[18];
  const float* Wval   = (const float*)d_in[19];
  const float* bval   = (const float*)d_in[20];
  const float* Wout   = (const float*)d_in[21];
  const float* bout   = (const float*)d_in[22];
  const float* Wf     = (const float*)d_in[23];
  const float* bf     = (const float*)d_in[24];
  const float* gf     = (const float*)d_in[25];
  const float* betaf  = (const float*)d_in[26];
  float* out = (float*)d_out;

  k_SS <<<NBB, NT>>>(pf, grid, Wk, bk, gk, betak, Wt, bt, imf, Wval, bval);
  k_knn<<<NPTS/4, 128>>>(grid);
  k_EG <<<NBB, NT>>>(grid, Wfc, gfc, betafc, gt, betat,
                     Woff, boff, Wattn, battn, Wout, bout, Wf, bf,
                     gf, betaf, out);
}

// round 11
// speedup vs baseline: 1.5022x; 1.5022x over previous
#include <cuda_runtime.h>

#define NPTS 16384
#define CC 16
#define HH 256
#define WW 704
#define HWIMG (HH*WW)        // 180224
#define EPSBN 1e-3f
#define NBB 128              // persistent blocks (<=148 SMs -> co-resident)
#define NT 512               // threads/block (4 threads per point)
#define NW 16                // warps/block
#define PPB 128              // points per block
#define INVN (1.0f/16384.0f)
#define NSX 44               // supercells per row (704/16)
#define NSC (HH*NSX)         // 11264 = 128*88
#define CHUNK 88
#define KNNR 10
#define KNNTH 120ULL
#define FULLM 0xffffffffu

// ------------------------- device scratch ----------------------------------
__device__ __align__(16) float g_val[HWIMG*CC];
__device__ __align__(16) float g_neigh[NPTS*CC];
__device__ __align__(16) float g_pts[NPTS*CC];
__device__ __align__(16) float g_Y3[NPTS*CC];
__device__ float g_pA[34*NBB];       // transposed: [item][block]
__device__ float g_p2[37*NBB];
__device__ float g_p3[32*NBB];
__device__ int g_cellCnt[NSC];       // zero-init; self-zeroing (scatter drains)
__device__ int g_cellStart[NSC+1];
__device__ int g_bs[NBB];
__device__ unsigned g_packed[NPTS];  // (idx<<18)|(y<<10)|x, grouped by supercell
__device__ int g_bc[4];              // phase barrier counters (self-resetting)

__device__ __forceinline__ float warpSum(float v){
#pragma unroll
  for(int o=16;o>0;o>>=1) v += __shfl_down_sync(FULLM, v, o);
  return v;
}
__device__ __forceinline__ int warpSumI(int v){
#pragma unroll
  for(int o=16;o>0;o>>=1) v += __shfl_down_sync(FULLM, v, o);
  return v;
}
__device__ __forceinline__ float warpMax(float v){
#pragma unroll
  for(int o=16;o>0;o>>=1) v = fmaxf(v, __shfl_down_sync(FULLM, v, o));
  return v;
}

// grid barrier across NBB resident blocks
__device__ __forceinline__ void gbar(int idx){
  __syncthreads();
  if(threadIdx.x==0){
    __threadfence();
    atomicAdd(&g_bc[idx], 1);
    while(((volatile int*)g_bc)[idx] < NBB) __nanosleep(32);
    __threadfence();
  }
  __syncthreads();
}

// ------------------------- K0: value table (wide grid, 1 pixel/thread) -----
__global__ void __launch_bounds__(128) k_init(const float* __restrict__ imf,
                                              const float* __restrict__ Wval,
                                              const float* __restrict__ bval){
  __shared__ float sW[CC*CC];
  __shared__ float sb[CC];
  int t = threadIdx.x;
  for(int i=t;i<CC*CC;i+=128) sW[i]=Wval[i];
  if(t<CC) sb[t]=bval[t];
  __syncthreads();
  int p = blockIdx.x*128 + t;
  float x[CC];
#pragma unroll
  for(int c=0;c<CC;c++) x[c] = imf[c*HWIMG + p];
  float o[CC];
#pragma unroll
  for(int j=0;j<CC;j++){
    float s=sb[j];
#pragma unroll
    for(int c=0;c<CC;c++) s += x[c]*sW[c*CC+j];
    o[j]=s;
  }
  float4* dst = (float4*)(g_val + p*CC);
  dst[0]=make_float4(o[0],o[1],o[2],o[3]);
  dst[1]=make_float4(o[4],o[5],o[6],o[7]);
  dst[2]=make_float4(o[8],o[9],o[10],o[11]);
  dst[3]=make_float4(o[12],o[13],o[14],o[15]);
}

// ------------------------- K1: persistent A + scan + scatter + C ------------
__global__ void __launch_bounds__(NT) k_SS(const float* __restrict__ pf,
    const int* __restrict__ grid,
    const float* __restrict__ Wk, const float* __restrict__ bk,
    const float* __restrict__ gk, const float* __restrict__ betak,
    const float* __restrict__ Wt, const float* __restrict__ bt){
  __shared__ float sW[CC*CC];
  __shared__ float sb[CC];
  __shared__ float red[NW][37];
  __shared__ int sredI[NW];
  __shared__ float sA[34];
  __shared__ float sa1[CC], sb1[CC], scc[2];
  int b=blockIdx.x, t=threadIdx.x;
  int lane=t&31, w=t>>5, r=t&3;
  int gbase = (lane&~3);
  if(b==0 && t==0) *(volatile int*)&g_bc[3] = 0;

  for(int i=t;i<CC*CC;i+=NT) sW[i]=Wk[i];
  if(t<CC) sb[t]=bk[t];
  __syncthreads();

  // ---- P0: count + Y1 (4 threads/point; thread owns channels 4r..4r+3) ----
  int n = b*PPB + (t>>2);
  int gyi = grid[2*n], gxi = grid[2*n+1];
  if(r==0) atomicAdd(&g_cellCnt[gyi*NSX + (gxi>>4)], 1);
  float x4[4];
  { float4 xv = *(const float4*)(pf + n*CC + 4*r);
    x4[0]=xv.x; x4[1]=xv.y; x4[2]=xv.z; x4[3]=xv.w; }
  float y4v[4];
#pragma unroll
  for(int j=0;j<4;j++) y4v[j]=sb[4*r+j];
#pragma unroll
  for(int rr=0;rr<4;rr++){
    float xs[4];
#pragma unroll
    for(int k=0;k<4;k++) xs[k]=__shfl_sync(FULLM, x4[k], gbase+rr);
#pragma unroll
    for(int k=0;k<4;k++)
#pragma unroll
      for(int j=0;j<4;j++) y4v[j] += xs[k]*sW[(4*rr+k)*CC + 4*r+j];
  }
  {
    float s1[4], s2[4];
#pragma unroll
    for(int j=0;j<4;j++){ s1[j]=y4v[j]; s2[j]=y4v[j]*y4v[j]; }
#pragma unroll
    for(int o=4;o<32;o<<=1)
#pragma unroll
      for(int j=0;j<4;j++){
        s1[j]+=__shfl_down_sync(FULLM,s1[j],o);
        s2[j]+=__shfl_down_sync(FULLM,s2[j],o);
      }
    if(lane<4)
#pragma unroll
      for(int j=0;j<4;j++){ red[w][4*lane+j]=s1[j]; red[w][16+4*lane+j]=s2[j]; }
    float gy=(r==0)?(float)gyi:0.f, gx=(r==0)?(float)gxi:0.f;
    float sgy=warpSum(gy), sgx=warpSum(gx);
    if(!lane){ red[w][32]=sgy; red[w][33]=sgx; }
  }
  __syncthreads();
  if(t<34){
    float s=0.f;
#pragma unroll
    for(int k=0;k<NW;k++) s += red[k][t];
    g_pA[t*NBB+b] = s;
  }
  gbar(0);

  // ---- P1: warp-0 scan of this block's 88 supercell counts ----
  int cbase = b*CHUNK;
  if(w==0){
    int base3 = lane*3;
    int loc[3]; int s=0;
#pragma unroll
    for(int i=0;i<3;i++){
      loc[i]=s;
      int idx=base3+i;
      if(idx<CHUNK) s += g_cellCnt[cbase+idx];
    }
    int incl=s;
#pragma unroll
    for(int o=1;o<32;o<<=1){ int xx=__shfl_up_sync(FULLM,incl,o); if(lane>=o) incl+=xx; }
    int pref = incl - s;
#pragma unroll
    for(int i=0;i<3;i++){
      int idx=base3+i;
      if(idx<CHUNK) g_cellStart[cbase+idx] = pref + loc[i];
    }
    if(lane==31) g_bs[b] = incl;
  }
  gbar(1);

  // ---- P2: add block offsets ----
  {
    int vb = (t<b) ? g_bs[t] : 0;
    int s = warpSumI(vb);
    if(!lane) sredI[w]=s;
    __syncthreads();
    int off=0;
#pragma unroll
    for(int k=0;k<NW;k++) off += sredI[k];
    if(t<CHUNK) g_cellStart[cbase+t] += off;
    if(b==0 && t==0) g_cellStart[NSC]=NPTS;
  }
  gbar(2);

  // ---- P3: stats finalize + scatter + pts/Y3 + p2 partials ----
  for(int i=w;i<34;i+=NW){
    const float* pp = g_pA + i*NBB;
    float s = pp[lane]+pp[lane+32]+pp[lane+64]+pp[lane+96];
    s = warpSum(s);
    if(!lane) sA[i]=s;
  }
  for(int i=t;i<CC*CC;i+=NT) sW[i]=Wt[i];
  if(t<CC) sb[t]=bt[t];
  __syncthreads();
  if(t<CC){
    float m = sA[t]*INVN;
    float vv = sA[16+t]*INVN - m*m;
    float is = rsqrtf(vv+EPSBN);
    sa1[t] = is*gk[t];
    sb1[t] = betak[t] - m*is*gk[t];
  }
  if(t==16) scc[0]=sA[32]*INVN;
  if(t==17) scc[1]=sA[33]*INVN;
  __syncthreads();
  if(r==0){
    int cid = gyi*NSX + (gxi>>4);
    int old = atomicSub(&g_cellCnt[cid], 1);   // drains to 0 (replay-safe)
    g_packed[g_cellStart[cid] + old - 1] =
        ((unsigned)n<<18) | ((unsigned)gyi<<10) | (unsigned)gxi;
  }
  float p4[4];
#pragma unroll
  for(int j=0;j<4;j++) p4[j] = y4v[j]*sa1[4*r+j] + sb1[4*r+j];
  *(float4*)(g_pts + n*CC + 4*r) = make_float4(p4[0],p4[1],p4[2],p4[3]);
  float y3[4];
#pragma unroll
  for(int j=0;j<4;j++) y3[j]=sb[4*r+j];
#pragma unroll
  for(int rr=0;rr<4;rr++){
    float xs[4];
#pragma unroll
    for(int k=0;k<4;k++) xs[k]=__shfl_sync(FULLM, p4[k], gbase+rr);
#pragma unroll
    for(int k=0;k<4;k++)
#pragma unroll
      for(int j=0;j<4;j++) y3[j] += xs[k]*sW[(4*rr+k)*CC + 4*r+j];
  }
  *(float4*)(g_Y3 + n*CC + 4*r) = make_float4(y3[0],y3[1],y3[2],y3[3]);
  {
    float s1[4], s2[4];
#pragma unroll
    for(int j=0;j<4;j++){ s1[j]=y3[j]; s2[j]=y3[j]*y3[j]; }
#pragma unroll
    for(int o=4;o<32;o<<=1)
#pragma unroll
      for(int j=0;j<4;j++){
        s1[j]+=__shfl_down_sync(FULLM,s1[j],o);
        s2[j]+=__shfl_down_sync(FULLM,s2[j],o);
      }
    if(lane<4)
#pragma unroll
      for(int j=0;j<4;j++){ red[w][4*lane+j]=s1[j]; red[w][16+4*lane+j]=s2[j]; }
    float ry=(float)gyi-scc[0], rx=(float)gxi-scc[1];
    float vyy=(r==0)?ry*ry:0.f, vxx=(r==0)?rx*rx:0.f, vxy=(r==0)?ry*rx:0.f;
    float myy=(r==0)?fabsf(ry):0.f, mxx2=(r==0)?fabsf(rx):0.f;
    float a_=warpSum(vyy); if(!lane) red[w][32]=a_;
    float b_=warpSum(vxx); if(!lane) red[w][33]=b_;
    float c_=warpSum(vxy); if(!lane) red[w][34]=c_;
    float d_=warpMax(myy); if(!lane) red[w][35]=d_;
    float e_=warpMax(mxx2); if(!lane) red[w][36]=e_;
  }
  __syncthreads();
  if(t<35){
    float s=0.f;
#pragma unroll
    for(int k=0;k<NW;k++) s += red[k][t];
    g_p2[t*NBB+b]=s;
  } else if(t<37){
    float m=0.f;
#pragma unroll
    for(int k=0;k<NW;k++) m = fmaxf(m, red[k][t]);
    g_p2[t*NBB+b]=m;
  }
}

// ------------------------- KNN helpers --------------------------------------
__device__ __forceinline__ unsigned long long umin64(unsigned long long a, unsigned long long b){
  return a<b ? a : b;
}
__device__ __forceinline__ unsigned long long umax64(unsigned long long a, unsigned long long b){
  return a<b ? b : a;
}
#define INS9(L0,L1,L2,L3,L4,L5,L6,L7,L8,KEY) do{ \
  unsigned long long _k=(KEY); \
  if(_k < L8){ \
    unsigned long long _t; \
    _t=L0; L0=umin64(_t,_k); _k=umax64(_t,_k); \
    _t=L1; L1=umin64(_t,_k); _k=umax64(_t,_k); \
    _t=L2; L2=umin64(_t,_k); _k=umax64(_t,_k); \
    _t=L3; L3=umin64(_t,_k); _k=umax64(_t,_k); \
    _t=L4; L4=umin64(_t,_k); _k=umax64(_t,_k); \
    _t=L5; L5=umin64(_t,_k); _k=umax64(_t,_k); \
    _t=L6; L6=umin64(_t,_k); _k=umax64(_t,_k); \
    _t=L7; L7=umin64(_t,_k); _k=umax64(_t,_k); \
    L8=umin64(L8,_k); \
  } }while(0)

__device__ __forceinline__ int isqrt_dev(int v){
  if(v < 0) return -1;
  int h = (int)sqrtf((float)v);
  while((h+1)*(h+1) <= v) h++;
  while(h>0 && h*h > v) h--;
  return h;
}

__device__ __forceinline__ unsigned long long mkkey(unsigned p, int qy, int qx){
  int dy = (int)((p>>10)&0xFFu) - qy;
  int dx = (int)(p&0x3FFu) - qx;
  return ((unsigned long long)(unsigned)(dy*dy+dx*dx) << 32) | p;
}

// ------------------------- K2: warp-per-query KNN + neighbor mean -----------
__global__ void __launch_bounds__(128) k_knn(const int* __restrict__ grid,
                                             const float* __restrict__ imf){
  int lane = threadIdx.x & 31;
  int n = blockIdx.x*4 + (threadIdx.x >> 5);
  int qy = __ldg(&grid[2*n]), qx = __ldg(&grid[2*n+1]);

  unsigned long long l0=~0ULL,l1=~0ULL,l2=~0ULL,l3=~0ULL,l4=~0ULL,
                     l5=~0ULL,l6=~0ULL,l7=~0ULL,l8=~0ULL;
  int row = qy - KNNR + lane;
  int s=0, e=0;
  if(lane < 2*KNNR+1 && row >= 0 && row < HH){
    int sxlo = max(qx-KNNR,0) >> 4;
    int sxhi = min(qx+KNNR,WW-1) >> 4;
    s = g_cellStart[row*NSX + sxlo];
    e = g_cellStart[row*NSX + sxhi + 1];
  }
  while(__any_sync(FULLM, s<e)){
    if(s<e){
      unsigned p = g_packed[s]; s++;
      unsigned long long key = mkkey(p, qy, qx);
      INS9(l0,l1,l2,l3,l4,l5,l6,l7,l8,key);
    }
  }
  unsigned long long w0,w1,w2,w3,w4,w5,w6,w7,w8;
#define ROUND(WR) { \
    unsigned long long m=l0; \
    _Pragma("unroll") \
    for(int o=16;o>0;o>>=1){ unsigned long long t2=__shfl_xor_sync(FULLM,m,o); if(t2<m)m=t2; } \
    WR = m; \
    if(l0==m){ l0=l1;l1=l2;l2=l3;l3=l4;l4=l5;l5=l6;l6=l7;l7=l8;l8=~0ULL; } }
  ROUND(w0) ROUND(w1) ROUND(w2) ROUND(w3) ROUND(w4)
  ROUND(w5) ROUND(w6) ROUND(w7) ROUND(w8)
#undef ROUND

  if(w8 == ~0ULL || (w8>>32) > KNNTH){
    unsigned long long f0=~0ULL,f1=~0ULL,f2=~0ULL,f3=~0ULL,f4=~0ULL,
                       f5=~0ULL,f6=~0ULL,f7=~0ULL,f8=~0ULL;
    if(lane==0){
      for(int d=0; d<HH; d++){
        if(f8 != ~0ULL && (unsigned long long)(d*d) > (f8>>32)) break;
        for(int sgn=0; sgn<2; sgn++){
          if(d==0 && sgn) break;
          int yy = sgn ? qy+d : qy-d;
          if((unsigned)yy >= HH) continue;
          int xlo=0, xhi=WW-1;
          if(f8 != ~0ULL){
            int vv = (int)(f8>>32) - d*d;
            if(vv < 0) continue;
            int hw = isqrt_dev(vv);
            xlo = max(qx-hw,0); xhi = min(qx+hw,WW-1);
          }
          int ss = g_cellStart[yy*NSX + (xlo>>4)];
          int ee = g_cellStart[yy*NSX + (xhi>>4) + 1];
          for(; ss<ee; ss++){
            unsigned long long key = mkkey(g_packed[ss], qy, qx);
            INS9(f0,f1,f2,f3,f4,f5,f6,f7,f8,key);
          }
        }
      }
    }
    w1=__shfl_sync(FULLM,f1,0); w2=__shfl_sync(FULLM,f2,0);
    w3=__shfl_sync(FULLM,f3,0); w4=__shfl_sync(FULLM,f4,0); w5=__shfl_sync(FULLM,f5,0);
    w6=__shfl_sync(FULLM,f6,0); w7=__shfl_sync(FULLM,f7,0); w8=__shfl_sync(FULLM,f8,0);
  }

  unsigned p1=(unsigned)w1, p2=(unsigned)w2, p3=(unsigned)w3, p4=(unsigned)w4,
           p5=(unsigned)w5, p6=(unsigned)w6, p7=(unsigned)w7, p8=(unsigned)w8;
#define POS(P) ((int)(((P)>>10)&0xFFu)*WW + (int)((P)&0x3FFu))
  int o1=POS(p1),o2=POS(p2),o3=POS(p3),o4=POS(p4),
      o5=POS(p5),o6=POS(p6),o7=POS(p7),o8=POS(p8);
#undef POS
  int ni = lane>>2;                 // neighbor group 0..7 -> winner ni+1
  int off = o1;
  off = (ni==1)?o2:off; off = (ni==2)?o3:off; off = (ni==3)?o4:off;
  off = (ni==4)?o5:off; off = (ni==5)?o6:off; off = (ni==6)?o7:off;
  off = (ni==7)?o8:off;
  // gather 4 channels (lane&3)*4 .. +3 directly from channel-major imf
  const float* base = imf + (lane&3)*4*HWIMG + off;
  float4 v;
  v.x = __ldg(base + 0*HWIMG);
  v.y = __ldg(base + 1*HWIMG);
  v.z = __ldg(base + 2*HWIMG);
  v.w = __ldg(base + 3*HWIMG);
#pragma unroll
  for(int o=4;o<=16;o<<=1){
    v.x += __shfl_xor_sync(FULLM, v.x, o);
    v.y += __shfl_xor_sync(FULLM, v.y, o);
    v.z += __shfl_xor_sync(FULLM, v.z, o);
    v.w += __shfl_xor_sync(FULLM, v.w, o);
  }
  if(lane < 4){
    v.x*=0.125f; v.y*=0.125f; v.z*=0.125f; v.w*=0.125f;
    ((float4*)(g_neigh + n*CC))[lane] = v;
  }
}

// ------------------------- K3: deform attn + fuse + final BN (4 thr/point) --
__global__ void __launch_bounds__(NT) k_EG(const int* __restrict__ grid,
    const float* __restrict__ Wfc, const float* __restrict__ gfc, const float* __restrict__ betafc,
    const float* __restrict__ gt,  const float* __restrict__ betat,
    const float* __restrict__ Woff,const float* __restrict__ boff,
    const float* __restrict__ Wattn,const float* __restrict__ battn,
    const float* __restrict__ Wout,const float* __restrict__ bout,
    const float* __restrict__ Wf,  const float* __restrict__ bf,
    const float* __restrict__ gf,  const float* __restrict__ betaf,
    float* __restrict__ out){
  __shared__ float sF[40];
  __shared__ float sWoff[CC*32], sWattn[CC*16], sWout[CC*16], sWf[32*CC];
  __shared__ float sboff[32], sbattn[16], sbout[16], sbf[16];
  __shared__ float sa3[16], sb3[16], su0[16], su1[16], sb2[16], sc[2];
  __shared__ float red[NW][32];
  __shared__ float sP[32], a4[16], b4[16];
  int b=blockIdx.x, t=threadIdx.x;
  int lane=t&31, w=t>>5, r=t&3;
  int gbase = (lane&~3);
  if(b==0 && t==0){
    *(volatile int*)&g_bc[0]=0;
    *(volatile int*)&g_bc[1]=0;
    *(volatile int*)&g_bc[2]=0;
  }
  for(int i=t;i<CC*32;i+=NT) sWoff[i]=Woff[i];
  for(int i=t;i<CC*16;i+=NT){ sWattn[i]=Wattn[i]; sWout[i]=Wout[i]; }
  for(int i=t;i<32*CC;i+=NT) sWf[i]=Wf[i];
  if(t<32) sboff[t]=boff[t];
  if(t<16){ sbattn[t]=battn[t]; sbout[t]=bout[t]; sbf[t]=bf[t]; }
  for(int i=w;i<35;i+=NW){
    const float* pp = g_p2 + i*NBB;
    float s = pp[lane]+pp[lane+32]+pp[lane+64]+pp[lane+96];
    s = warpSum(s);
    if(!lane) sF[i]=s;
  }
  if(w==4){
    const float* pp = g_p2 + 35*NBB;
    float m = fmaxf(fmaxf(pp[lane],pp[lane+32]),fmaxf(pp[lane+64],pp[lane+96]));
    m = warpMax(m);
    if(!lane) sF[35]=m;
  } else if(w==5){
    const float* pp = g_p2 + 36*NBB;
    float m = fmaxf(fmaxf(pp[lane],pp[lane+32]),fmaxf(pp[lane+64],pp[lane+96]));
    m = warpMax(m);
    if(!lane) sF[36]=m;
  } else if(w==6){
    const float* pp = g_pA + 32*NBB;
    float s = pp[lane]+pp[lane+32]+pp[lane+64]+pp[lane+96];
    s = warpSum(s);
    if(!lane) sF[37]=s;
  } else if(w==7){
    const float* pp = g_pA + 33*NBB;
    float s = pp[lane]+pp[lane+32]+pp[lane+64]+pp[lane+96];
    s = warpSum(s);
    if(!lane) sF[38]=s;
  }
  __syncthreads();
  if(t<16){
    float m3 = sF[t]*INVN;
    float v3 = sF[16+t]*INVN - m3*m3;
    float is3 = rsqrtf(v3+EPSBN);
    sa3[t] = is3*gt[t];
    sb3[t] = betat[t] - m3*is3*gt[t];
    float mxy = sF[35]; if(mxy==0.f) mxy=1.f;
    float mxx = sF[36]; if(mxx==0.f) mxx=1.f;
    float Syy=sF[32]*INVN, Sxx=sF[33]*INVN, Sxy=sF[34]*INVN;
    float w0 = Wfc[t]/mxy;
    float w1 = Wfc[16+t]/mxx;
    float v2 = w0*w0*Syy + 2.f*w0*w1*Sxy + w1*w1*Sxx;
    float a2 = rsqrtf(v2+EPSBN)*gfc[t];
    su0[t]=w0*a2; su1[t]=w1*a2; sb2[t]=betafc[t];
  }
  if(t==16){ sc[0]=sF[37]*INVN; sc[1]=sF[38]*INVN; }
  __syncthreads();

  int n = b*PPB + (t>>2);
  int qyi = grid[2*n], qxi = grid[2*n+1];
  float gy=(float)qyi, gx=(float)qxi;
  float ry=gy-sc[0], rx=gx-sc[1];
  float q4[4];
  { float4 pv = *(const float4*)(g_pts + n*CC + 4*r);
    q4[0]=pv.x+ry*su0[4*r+0]+rx*su1[4*r+0]+sb2[4*r+0];
    q4[1]=pv.y+ry*su0[4*r+1]+rx*su1[4*r+1]+sb2[4*r+1];
    q4[2]=pv.z+ry*su0[4*r+2]+rx*su1[4*r+2]+sb2[4*r+2];
    q4[3]=pv.w+ry*su0[4*r+3]+rx*su1[4*r+3]+sb2[4*r+3]; }

  // thread r owns head r: 4 logits + 8 offsets
  float lg[4], offy[4], offx[4];
#pragma unroll
  for(int p=0;p<4;p++){
    lg[p]=sbattn[4*r+p];
    offy[p]=sboff[r*8+p*2];
    offx[p]=sboff[r*8+p*2+1];
  }
#pragma unroll
  for(int rr=0;rr<4;rr++){
    float qs[4];
#pragma unroll
    for(int k=0;k<4;k++) qs[k]=__shfl_sync(FULLM, q4[k], gbase+rr);
#pragma unroll
    for(int k=0;k<4;k++){
      int c = 4*rr+k;
#pragma unroll
      for(int p=0;p<4;p++){
        lg[p]  += qs[k]*sWattn[c*16 + 4*r + p];
        offy[p]+= qs[k]*sWoff[c*32 + r*8 + p*2];
        offx[p]+= qs[k]*sWoff[c*32 + r*8 + p*2+1];
      }
    }
  }
  float mx=fmaxf(fmaxf(lg[0],lg[1]),fmaxf(lg[2],lg[3]));
  float e0=expf(lg[0]-mx), e1=expf(lg[1]-mx), e2=expf(lg[2]-mx), e3=expf(lg[3]-mx);
  float inv=1.f/(e0+e1+e2+e3);
  lg[0]=e0*inv; lg[1]=e1*inv; lg[2]=e2*inv; lg[3]=e3*inv;

  float acc4[4]={0.f,0.f,0.f,0.f};
#define CORNER(Yf,Xf,Wgt) do{ \
    float _y=(Yf), _x=(Xf); \
    if(_y>=0.f && _y<=(float)(HH-1) && _x>=0.f && _x<=(float)(WW-1)){ \
      int _i = ((int)_y)*WW + (int)_x; \
      const float4 _v = *(const float4*)(g_val + _i*CC + 4*r); \
      float _w=(Wgt); \
      acc4[0]+=_w*_v.x; acc4[1]+=_w*_v.y; acc4[2]+=_w*_v.z; acc4[3]+=_w*_v.w; \
    } }while(0)
#pragma unroll
  for(int p=0;p<4;p++){
    float ly=gy+offy[p], lx=gx+offx[p];
    float fy=floorf(ly), fx=floorf(lx);
    float wy=ly-fy, wx=lx-fx;
    float ap=lg[p];
    CORNER(fy,     fx,     ap*(1.f-wy)*(1.f-wx));
    CORNER(fy,     fx+1.f, ap*(1.f-wy)*wx);
    CORNER(fy+1.f, fx,     ap*wy*(1.f-wx));
    CORNER(fy+1.f, fx+1.f, ap*wy*wx);
  }
#undef CORNER

  float img4[4];
#pragma unroll
  for(int j=0;j<4;j++) img4[j]=sbout[4*r+j];
#pragma unroll
  for(int rr=0;rr<4;rr++){
    float as[4];
#pragma unroll
    for(int k=0;k<4;k++) as[k]=__shfl_sync(FULLM, acc4[k], gbase+rr);
#pragma unroll
    for(int k=0;k<4;k++)
#pragma unroll
      for(int j=0;j<4;j++) img4[j] += as[k]*sWout[(4*rr+k)*16 + 4*r+j];
  }
  { float4 nb = *(const float4*)(g_neigh + n*CC + 4*r);
    img4[0]+=nb.x; img4[1]+=nb.y; img4[2]+=nb.z; img4[3]+=nb.w; }

  float pp4[4];
  { float4 yv = *(const float4*)(g_Y3 + n*CC + 4*r);
    pp4[0]=yv.x*sa3[4*r+0]+sb3[4*r+0];
    pp4[1]=yv.y*sa3[4*r+1]+sb3[4*r+1];
    pp4[2]=yv.z*sa3[4*r+2]+sb3[4*r+2];
    pp4[3]=yv.w*sa3[4*r+3]+sb3[4*r+3]; }

  float y4f[4];
#pragma unroll
  for(int j=0;j<4;j++) y4f[j]=sbf[4*r+j];
#pragma unroll
  for(int rr=0;rr<4;rr++){
    float ps[4], is_[4];
#pragma unroll
    for(int k=0;k<4;k++){
      ps[k] =__shfl_sync(FULLM, pp4[k],  gbase+rr);
      is_[k]=__shfl_sync(FULLM, img4[k], gbase+rr);
    }
#pragma unroll
    for(int k=0;k<4;k++){
      float pv=fmaxf(ps[k],0.f), iv=fmaxf(is_[k],0.f);
#pragma unroll
      for(int j=0;j<4;j++)
        y4f[j] += pv*sWf[(4*rr+k)*16 + 4*r+j] + iv*sWf[(16+4*rr+k)*16 + 4*r+j];
    }
  }
  {
    float s1[4], s2[4];
#pragma unroll
    for(int j=0;j<4;j++){ s1[j]=y4f[j]; s2[j]=y4f[j]*y4f[j]; }
#pragma unroll
    for(int o=4;o<32;o<<=1)
#pragma unroll
      for(int j=0;j<4;j++){
        s1[j]+=__shfl_down_sync(FULLM,s1[j],o);
        s2[j]+=__shfl_down_sync(FULLM,s2[j],o);
      }
    if(lane<4)
#pragma unroll
      for(int j=0;j<4;j++){ red[w][4*lane+j]=s1[j]; red[w][16+4*lane+j]=s2[j]; }
  }
  __syncthreads();
  if(t<32){
    float s=0.f;
#pragma unroll
    for(int k=0;k<NW;k++) s += red[k][t];
    g_p3[t*NBB+b]=s;
  }

  gbar(3);

  // ---- final BN + relu (y4f still in registers) ----
  for(int i=w;i<32;i+=NW){
    const float* pp = g_p3 + i*NBB;
    float s = pp[lane]+pp[lane+32]+pp[lane+64]+pp[lane+96];
    s = warpSum(s);
    if(!lane) sP[i]=s;
  }
  __syncthreads();
  if(t<16){
    float m = sP[t]*INVN;
    float vv = sP[16+t]*INVN - m*m;
    float is = rsqrtf(vv+EPSBN);
    a4[t]=is*gf[t];
    b4[t]=betaf[t] - m*is*gf[t];
  }
  __syncthreads();
  float4 ov;
  ov.x = fmaxf(y4f[0]*a4[4*r+0]+b4[4*r+0], 0.f);
  ov.y = fmaxf(y4f[1]*a4[4*r+1]+b4[4*r+1], 0.f);
  ov.z = fmaxf(y4f[2]*a4[4*r+2]+b4[4*r+2], 0.f);
  ov.w = fmaxf(y4f[3]*a4[4*r+3]+b4[4*r+3], 0.f);
  *(float4*)(out + n*CC + 4*r) = ov;
}

// ------------------------- launch ------------------------------------------
extern "C" void kernel_launch(void* const* d_in, const int* in_sizes, int n_in,
                              void* d_out, int out_size){
  const float* pf     = (const float*)d_in[0];
  const float* imf    = (const float*)d_in[1];
  const int*   grid   = (const int*)  d_in[2];
  const float* Wk     = (const float*)d_in[3];
  const float* bk     = (const float*)d_in[4];
  const float* gk     = (const float*)d_in[5];
  const float* betak  = (const float*)d_in[6];
  const float* Wfc    = (const float*)d_in[7];
  /* bfc = d_in[8] cancels analytically */
  const float* gfc    = (const float*)d_in[9];
  const float* betafc = (const float*)d_in[10];
  const float* Wt     = (const float*)d_in[11];
  const float* bt     = (const float*)d_in[12];
  const float* gt     = (const float*)d_in[13];
  const float* betat  = (const float*)d_in[14];
  const float* Woff   = (const float*)d_in[15];
  const float* boff   = (const float*)d_in[16];
  const float* Wattn  = (const float*)d_in[17];
  const float* battn  = (const float*)d_in[18];
  const float* Wval   = (const float*)d_in[19];
  const float* bval   = (const float*)d_in[20];
  const float* Wout   = (const float*)d_in[21];
  const float* bout   = (const float*)d_in[22];
  const float* Wf     = (const float*)d_in[23];
  const float* bf     = (const float*)d_in[24];
  const float* gf     = (const float*)d_in[25];
  const float* betaf  = (const float*)d_in[26];
  float* out = (float*)d_out;

  k_init<<<HWIMG/128, 128>>>(imf, Wval, bval);
  k_SS <<<NBB, NT>>>(pf, grid, Wk, bk, gk, betak, Wt, bt);
  k_knn<<<NPTS/4, 128>>>(grid, imf);
  k_EG <<<NBB, NT>>>(grid, Wfc, gfc, betafc, gt, betat,
                     Woff, boff, Wattn, battn, Wout, bout, Wf, bf,
                     gf, betaf, out);
}

// round 13
// speedup vs baseline: 1.5093x; 1.0048x over previous
#include <cuda_runtime.h>

#define NPTS 16384
#define CC 16
#define HH 256
#define WW 704
#define HWIMG (HH*WW)        // 180224
#define EPSBN 1e-3f
#define NBB 128              // persistent blocks (<=148 SMs -> co-resident)
#define NT 512               // threads/block (4 threads per point)
#define NW 16                // warps/block
#define PPB 128              // points per block
#define INVN (1.0f/16384.0f)
#define NSX 44               // supercells per row (704/16)
#define NSC (HH*NSX)         // 11264 = 128*88
#define CHUNK 88
#define KNNR 10
#define KNNTH 120ULL
#define FULLM 0xffffffffu

// ------------------------- device scratch ----------------------------------
__device__ __align__(16) float g_val[HWIMG*CC];
__device__ __align__(16) float g_neigh[NPTS*CC];
__device__ __align__(16) float g_pts[NPTS*CC];
__device__ __align__(16) float g_Y3[NPTS*CC];
__device__ float g_pA[34*NBB];       // transposed: [item][block]
__device__ float g_p2[37*NBB];
__device__ float g_p3[32*NBB];
__device__ int g_cellCnt[NSC];       // zero-init; self-zeroing (scatter drains)
__device__ int g_cellStart[NSC+1];
__device__ int g_bs[NBB];
__device__ unsigned g_packed[NPTS];  // (idx<<18)|(y<<10)|x, grouped by supercell
__device__ int g_bc[4];              // phase barrier counters (self-resetting)

__device__ __forceinline__ float warpSum(float v){
#pragma unroll
  for(int o=16;o>0;o>>=1) v += __shfl_down_sync(FULLM, v, o);
  return v;
}
__device__ __forceinline__ int warpSumI(int v){
#pragma unroll
  for(int o=16;o>0;o>>=1) v += __shfl_down_sync(FULLM, v, o);
  return v;
}
__device__ __forceinline__ float warpMax(float v){
#pragma unroll
  for(int o=16;o>0;o>>=1) v = fmaxf(v, __shfl_down_sync(FULLM, v, o));
  return v;
}

// grid barrier across NBB resident blocks
__device__ __forceinline__ void gbar(int idx){
  __syncthreads();
  if(threadIdx.x==0){
    __threadfence();
    atomicAdd(&g_bc[idx], 1);
    while(((volatile int*)g_bc)[idx] < NBB) __nanosleep(32);
    __threadfence();
  }
  __syncthreads();
}

// ------------------------- K1: persistent A + scan + scatter + C ------------
__global__ void __launch_bounds__(NT) k_SS(const float* __restrict__ pf,
    const int* __restrict__ grid,
    const float* __restrict__ Wk, const float* __restrict__ bk,
    const float* __restrict__ gk, const float* __restrict__ betak,
    const float* __restrict__ Wt, const float* __restrict__ bt){
  __shared__ float sW[CC*CC];
  __shared__ float sb[CC];
  __shared__ float red[NW][37];
  __shared__ int sredI[NW];
  __shared__ float sA[34];
  __shared__ float sa1[CC], sb1[CC], scc[2];
  int b=blockIdx.x, t=threadIdx.x;
  int lane=t&31, w=t>>5, r=t&3;
  int gbase = (lane&~3);

  // prefetch per-point data FIRST (hide latency behind smem staging)
  int n = b*PPB + (t>>2);
  int gyi = __ldg(&grid[2*n]), gxi = __ldg(&grid[2*n+1]);
  float4 xv = __ldg((const float4*)(pf + n*CC + 4*r));

  if(b==0 && t==0) *(volatile int*)&g_bc[3] = 0;
  for(int i=t;i<CC*CC;i+=NT) sW[i]=Wk[i];
  if(t<CC) sb[t]=bk[t];
  __syncthreads();

  // ---- P0: count + Y1 (4 threads/point; thread owns channels 4r..4r+3) ----
  if(r==0) atomicAdd(&g_cellCnt[gyi*NSX + (gxi>>4)], 1);
  float x4[4] = {xv.x, xv.y, xv.z, xv.w};
  float y4v[4];
#pragma unroll
  for(int j=0;j<4;j++) y4v[j]=sb[4*r+j];
#pragma unroll
  for(int rr=0;rr<4;rr++){
    float xs[4];
#pragma unroll
    for(int k=0;k<4;k++) xs[k]=__shfl_sync(FULLM, x4[k], gbase+rr);
#pragma unroll
    for(int k=0;k<4;k++)
#pragma unroll
      for(int j=0;j<4;j++) y4v[j] += xs[k]*sW[(4*rr+k)*CC + 4*r+j];
  }
  {
    float s1[4], s2[4];
#pragma unroll
    for(int j=0;j<4;j++){ s1[j]=y4v[j]; s2[j]=y4v[j]*y4v[j]; }
#pragma unroll
    for(int o=4;o<32;o<<=1)
#pragma unroll
      for(int j=0;j<4;j++){
        s1[j]+=__shfl_down_sync(FULLM,s1[j],o);
        s2[j]+=__shfl_down_sync(FULLM,s2[j],o);
      }
    if(lane<4)
#pragma unroll
      for(int j=0;j<4;j++){ red[w][4*lane+j]=s1[j]; red[w][16+4*lane+j]=s2[j]; }
    float gy=(r==0)?(float)gyi:0.f, gx=(r==0)?(float)gxi:0.f;
    float sgy=warpSum(gy), sgx=warpSum(gx);
    if(!lane){ red[w][32]=sgy; red[w][33]=sgx; }
  }
  __syncthreads();
  if(t<34){
    float s=0.f;
#pragma unroll
    for(int k=0;k<NW;k++) s += red[k][t];
    g_pA[t*NBB+b] = s;
  }
  gbar(0);

  // ---- P1: warp-0 scan of this block's 88 supercell counts ----
  int cbase = b*CHUNK;
  if(w==0){
    int base3 = lane*3;
    int loc[3]; int s=0;
#pragma unroll
    for(int i=0;i<3;i++){
      loc[i]=s;
      int idx=base3+i;
      if(idx<CHUNK) s += g_cellCnt[cbase+idx];
    }
    int incl=s;
#pragma unroll
    for(int o=1;o<32;o<<=1){ int xx=__shfl_up_sync(FULLM,incl,o); if(lane>=o) incl+=xx; }
    int pref = incl - s;
#pragma unroll
    for(int i=0;i<3;i++){
      int idx=base3+i;
      if(idx<CHUNK) g_cellStart[cbase+idx] = pref + loc[i];
    }
    if(lane==31) g_bs[b] = incl;
  }
  gbar(1);

  // ---- P2: add block offsets ----
  {
    int vb = (t<b) ? g_bs[t] : 0;
    int s = warpSumI(vb);
    if(!lane) sredI[w]=s;
    __syncthreads();
    int off=0;
#pragma unroll
    for(int k=0;k<NW;k++) off += sredI[k];
    if(t<CHUNK) g_cellStart[cbase+t] += off;
    if(b==0 && t==0) g_cellStart[NSC]=NPTS;
  }
  gbar(2);

  // ---- P3: stats finalize + scatter + pts/Y3 + p2 partials ----
  for(int i=w;i<34;i+=NW){
    const float* pp = g_pA + i*NBB;
    float s = pp[lane]+pp[lane+32]+pp[lane+64]+pp[lane+96];
    s = warpSum(s);
    if(!lane) sA[i]=s;
  }
  for(int i=t;i<CC*CC;i+=NT) sW[i]=Wt[i];
  if(t<CC) sb[t]=bt[t];
  __syncthreads();
  if(t<CC){
    float m = sA[t]*INVN;
    float vv = sA[16+t]*INVN - m*m;
    float is = rsqrtf(vv+EPSBN);
    sa1[t] = is*gk[t];
    sb1[t] = betak[t] - m*is*gk[t];
  }
  if(t==16) scc[0]=sA[32]*INVN;
  if(t==17) scc[1]=sA[33]*INVN;
  __syncthreads();
  if(r==0){
    int cid = gyi*NSX + (gxi>>4);
    int old = atomicSub(&g_cellCnt[cid], 1);   // drains to 0 (replay-safe)
    g_packed[g_cellStart[cid] + old - 1] =
        ((unsigned)n<<18) | ((unsigned)gyi<<10) | (unsigned)gxi;
  }
  float p4[4];
#pragma unroll
  for(int j=0;j<4;j++) p4[j] = y4v[j]*sa1[4*r+j] + sb1[4*r+j];
  *(float4*)(g_pts + n*CC + 4*r) = make_float4(p4[0],p4[1],p4[2],p4[3]);
  float y3[4];
#pragma unroll
  for(int j=0;j<4;j++) y3[j]=sb[4*r+j];
#pragma unroll
  for(int rr=0;rr<4;rr++){
    float xs[4];
#pragma unroll
    for(int k=0;k<4;k++) xs[k]=__shfl_sync(FULLM, p4[k], gbase+rr);
#pragma unroll
    for(int k=0;k<4;k++)
#pragma unroll
      for(int j=0;j<4;j++) y3[j] += xs[k]*sW[(4*rr+k)*CC + 4*r+j];
  }
  *(float4*)(g_Y3 + n*CC + 4*r) = make_float4(y3[0],y3[1],y3[2],y3[3]);
  {
    float s1[4], s2[4];
#pragma unroll
    for(int j=0;j<4;j++){ s1[j]=y3[j]; s2[j]=y3[j]*y3[j]; }
#pragma unroll
    for(int o=4;o<32;o<<=1)
#pragma unroll
      for(int j=0;j<4;j++){
        s1[j]+=__shfl_down_sync(FULLM,s1[j],o);
        s2[j]+=__shfl_down_sync(FULLM,s2[j],o);
      }
    if(lane<4)
#pragma unroll
      for(int j=0;j<4;j++){ red[w][4*lane+j]=s1[j]; red[w][16+4*lane+j]=s2[j]; }
    float ry=(float)gyi-scc[0], rx=(float)gxi-scc[1];
    float vyy=(r==0)?ry*ry:0.f, vxx=(r==0)?rx*rx:0.f, vxy=(r==0)?ry*rx:0.f;
    float myy=(r==0)?fabsf(ry):0.f, mxx2=(r==0)?fabsf(rx):0.f;
    float a_=warpSum(vyy); if(!lane) red[w][32]=a_;
    float b_=warpSum(vxx); if(!lane) red[w][33]=b_;
    float c_=warpSum(vxy); if(!lane) red[w][34]=c_;
    float d_=warpMax(myy); if(!lane) red[w][35]=d_;
    float e_=warpMax(mxx2); if(!lane) red[w][36]=e_;
  }
  __syncthreads();
  if(t<35){
    float s=0.f;
#pragma unroll
    for(int k=0;k<NW;k++) s += red[k][t];
    g_p2[t*NBB+b]=s;
  } else if(t<37){
    float m=0.f;
#pragma unroll
    for(int k=0;k<NW;k++) m = fmaxf(m, red[k][t]);
    g_p2[t*NBB+b]=m;
  }
}

// ------------------------- KNN helpers --------------------------------------
__device__ __forceinline__ unsigned long long umin64(unsigned long long a, unsigned long long b){
  return a<b ? a : b;
}
__device__ __forceinline__ unsigned long long umax64(unsigned long long a, unsigned long long b){
  return a<b ? b : a;
}
#define INS9(L0,L1,L2,L3,L4,L5,L6,L7,L8,KEY) do{ \
  unsigned long long _k=(KEY); \
  if(_k < L8){ \
    unsigned long long _t; \
    _t=L0; L0=umin64(_t,_k); _k=umax64(_t,_k); \
    _t=L1; L1=umin64(_t,_k); _k=umax64(_t,_k); \
    _t=L2; L2=umin64(_t,_k); _k=umax64(_t,_k); \
    _t=L3; L3=umin64(_t,_k); _k=umax64(_t,_k); \
    _t=L4; L4=umin64(_t,_k); _k=umax64(_t,_k); \
    _t=L5; L5=umin64(_t,_k); _k=umax64(_t,_k); \
    _t=L6; L6=umin64(_t,_k); _k=umax64(_t,_k); \
    _t=L7; L7=umin64(_t,_k); _k=umax64(_t,_k); \
    L8=umin64(L8,_k); \
  } }while(0)

__device__ __forceinline__ int isqrt_dev(int v){
  if(v < 0) return -1;
  int h = (int)sqrtf((float)v);
  while((h+1)*(h+1) <= v) h++;
  while(h>0 && h*h > v) h--;
  return h;
}

__device__ __forceinline__ unsigned long long mkkey(unsigned p, int qy, int qx){
  int dy = (int)((p>>10)&0xFFu) - qy;
  int dx = (int)(p&0x3FFu) - qx;
  return ((unsigned long long)(unsigned)(dy*dy+dx*dx) << 32) | p;
}

// ------------------------- K2: value-table init + warp-per-query KNN --------
__global__ void __launch_bounds__(128) k_knn(const int* __restrict__ grid,
                                             const float* __restrict__ imf,
                                             const float* __restrict__ Wval,
                                             const float* __restrict__ bval){
  __shared__ float sW[CC*CC];
  __shared__ float sb[CC];
  int t = threadIdx.x;
  int lane = t & 31;
  // ---- init prologue: one pixel per thread (first 1408 blocks) ----
  int p = blockIdx.x*128 + t;
  if(p < HWIMG){
    for(int i=t;i<CC*CC;i+=128) sW[i]=Wval[i];
    if(t<CC) sb[t]=bval[t];
  }
  __syncthreads();
  if(p < HWIMG){
    float x[CC];
#pragma unroll
    for(int c=0;c<CC;c++) x[c] = __ldg(&imf[c*HWIMG + p]);
    float o[CC];
#pragma unroll
    for(int j=0;j<CC;j++){
      float s=sb[j];
#pragma unroll
      for(int c=0;c<CC;c++) s += x[c]*sW[c*CC+j];
      o[j]=s;
    }
    float4* dst = (float4*)(g_val + p*CC);
    dst[0]=make_float4(o[0],o[1],o[2],o[3]);
    dst[1]=make_float4(o[4],o[5],o[6],o[7]);
    dst[2]=make_float4(o[8],o[9],o[10],o[11]);
    dst[3]=make_float4(o[12],o[13],o[14],o[15]);
  }

  // ---- KNN: warp per query ----
  int n = blockIdx.x*4 + (t >> 5);
  int qy = __ldg(&grid[2*n]), qx = __ldg(&grid[2*n+1]);

  unsigned long long l0=~0ULL,l1=~0ULL,l2=~0ULL,l3=~0ULL,l4=~0ULL,
                     l5=~0ULL,l6=~0ULL,l7=~0ULL,l8=~0ULL;
  int row = qy - KNNR + lane;
  int s=0, e=0;
  if(lane < 2*KNNR+1 && row >= 0 && row < HH){
    int sxlo = max(qx-KNNR,0) >> 4;
    int sxhi = min(qx+KNNR,WW-1) >> 4;
    s = g_cellStart[row*NSX + sxlo];
    e = g_cellStart[row*NSX + sxhi + 1];
  }
  while(__any_sync(FULLM, s<e)){
    if(s<e){
      unsigned pk = g_packed[s]; s++;
      unsigned long long key = mkkey(pk, qy, qx);
      INS9(l0,l1,l2,l3,l4,l5,l6,l7,l8,key);
    }
  }
  unsigned long long w0,w1,w2,w3,w4,w5,w6,w7,w8;
#define ROUND(WR) { \
    unsigned long long m=l0; \
    _Pragma("unroll") \
    for(int o=16;o>0;o>>=1){ unsigned long long t2=__shfl_xor_sync(FULLM,m,o); if(t2<m)m=t2; } \
    WR = m; \
    if(l0==m){ l0=l1;l1=l2;l2=l3;l3=l4;l4=l5;l5=l6;l6=l7;l7=l8;l8=~0ULL; } }
  ROUND(w0) ROUND(w1) ROUND(w2) ROUND(w3) ROUND(w4)
  ROUND(w5) ROUND(w6) ROUND(w7) ROUND(w8)
#undef ROUND

  if(w8 == ~0ULL || (w8>>32) > KNNTH){
    unsigned long long f0=~0ULL,f1=~0ULL,f2=~0ULL,f3=~0ULL,f4=~0ULL,
                       f5=~0ULL,f6=~0ULL,f7=~0ULL,f8=~0ULL;
    if(lane==0){
      for(int d=0; d<HH; d++){
        if(f8 != ~0ULL && (unsigned long long)(d*d) > (f8>>32)) break;
        for(int sgn=0; sgn<2; sgn++){
          if(d==0 && sgn) break;
          int yy = sgn ? qy+d : qy-d;
          if((unsigned)yy >= HH) continue;
          int xlo=0, xhi=WW-1;
          if(f8 != ~0ULL){
            int vv = (int)(f8>>32) - d*d;
            if(vv < 0) continue;
            int hw = isqrt_dev(vv);
            xlo = max(qx-hw,0); xhi = min(qx+hw,WW-1);
          }
          int ss = g_cellStart[yy*NSX + (xlo>>4)];
          int ee = g_cellStart[yy*NSX + (xhi>>4) + 1];
          for(; ss<ee; ss++){
            unsigned long long key = mkkey(g_packed[ss], qy, qx);
            INS9(f0,f1,f2,f3,f4,f5,f6,f7,f8,key);
          }
        }
      }
    }
    w1=__shfl_sync(FULLM,f1,0); w2=__shfl_sync(FULLM,f2,0);
    w3=__shfl_sync(FULLM,f3,0); w4=__shfl_sync(FULLM,f4,0); w5=__shfl_sync(FULLM,f5,0);
    w6=__shfl_sync(FULLM,f6,0); w7=__shfl_sync(FULLM,f7,0); w8=__shfl_sync(FULLM,f8,0);
  }

  unsigned p1=(unsigned)w1, p2=(unsigned)w2, p3=(unsigned)w3, p4=(unsigned)w4,
           p5=(unsigned)w5, p6=(unsigned)w6, p7=(unsigned)w7, p8=(unsigned)w8;
#define POS(P) ((int)(((P)>>10)&0xFFu)*WW + (int)((P)&0x3FFu))
  int o1=POS(p1),o2=POS(p2),o3=POS(p3),o4=POS(p4),
      o5=POS(p5),o6=POS(p6),o7=POS(p7),o8=POS(p8);
#undef POS
  int ni = lane>>2;                 // neighbor group 0..7 -> winner ni+1
  int off = o1;
  off = (ni==1)?o2:off; off = (ni==2)?o3:off; off = (ni==3)?o4:off;
  off = (ni==4)?o5:off; off = (ni==5)?o6:off; off = (ni==6)?o7:off;
  off = (ni==7)?o8:off;
  const float* base = imf + (lane&3)*4*HWIMG + off;
  float4 v;
  v.x = __ldg(base + 0*HWIMG);
  v.y = __ldg(base + 1*HWIMG);
  v.z = __ldg(base + 2*HWIMG);
  v.w = __ldg(base + 3*HWIMG);
#pragma unroll
  for(int o=4;o<=16;o<<=1){
    v.x += __shfl_xor_sync(FULLM, v.x, o);
    v.y += __shfl_xor_sync(FULLM, v.y, o);
    v.z += __shfl_xor_sync(FULLM, v.z, o);
    v.w += __shfl_xor_sync(FULLM, v.w, o);
  }
  if(lane < 4){
    v.x*=0.125f; v.y*=0.125f; v.z*=0.125f; v.w*=0.125f;
    ((float4*)(g_neigh + n*CC))[lane] = v;
  }
}

// ------------------------- K3: deform attn + fuse + final BN (4 thr/point) --
__global__ void __launch_bounds__(NT) k_EG(const int* __restrict__ grid,
    const float* __restrict__ Wfc, const float* __restrict__ gfc, const float* __restrict__ betafc,
    const float* __restrict__ gt,  const float* __restrict__ betat,
    const float* __restrict__ Woff,const float* __restrict__ boff,
    const float* __restrict__ Wattn,const float* __restrict__ battn,
    const float* __restrict__ Wout,const float* __restrict__ bout,
    const float* __restrict__ Wf,  const float* __restrict__ bf,
    const float* __restrict__ gf,  const float* __restrict__ betaf,
    float* __restrict__ out){
  __shared__ float sF[40];
  __shared__ float sWoff[CC*32], sWattn[CC*16], sWout[CC*16], sWf[32*CC];
  __shared__ float sboff[32], sbattn[16], sbout[16], sbf[16];
  __shared__ float sa3[16], sb3[16], su0[16], su1[16], sb2[16], sc[2];
  __shared__ float red[NW][32];
  __shared__ float sP[32], a4[16], b4[16];
  int b=blockIdx.x, t=threadIdx.x;
  int lane=t&31, w=t>>5, r=t&3;
  int gbase = (lane&~3);

  // prefetch per-point data FIRST (hide latency behind smem staging + prologue)
  int n = b*PPB + (t>>2);
  int qyi = __ldg(&grid[2*n]), qxi = __ldg(&grid[2*n+1]);
  float4 pv = __ldg((const float4*)(g_pts + n*CC + 4*r));
  float4 yv = __ldg((const float4*)(g_Y3 + n*CC + 4*r));
  float4 nb = __ldg((const float4*)(g_neigh + n*CC + 4*r));

  if(b==0 && t==0){
    *(volatile int*)&g_bc[0]=0;
    *(volatile int*)&g_bc[1]=0;
    *(volatile int*)&g_bc[2]=0;
  }
  for(int i=t;i<CC*32;i+=NT) sWoff[i]=Woff[i];
  for(int i=t;i<CC*16;i+=NT){ sWattn[i]=Wattn[i]; sWout[i]=Wout[i]; }
  for(int i=t;i<32*CC;i+=NT) sWf[i]=Wf[i];
  if(t<32) sboff[t]=boff[t];
  if(t<16){ sbattn[t]=battn[t]; sbout[t]=bout[t]; sbf[t]=bf[t]; }
  for(int i=w;i<35;i+=NW){
    const float* pp = g_p2 + i*NBB;
    float s = pp[lane]+pp[lane+32]+pp[lane+64]+pp[lane+96];
    s = warpSum(s);
    if(!lane) sF[i]=s;
  }
  if(w==4){
    const float* pp = g_p2 + 35*NBB;
    float m = fmaxf(fmaxf(pp[lane],pp[lane+32]),fmaxf(pp[lane+64],pp[lane+96]));
    m = warpMax(m);
    if(!lane) sF[35]=m;
  } else if(w==5){
    const float* pp = g_p2 + 36*NBB;
    float m = fmaxf(fmaxf(pp[lane],pp[lane+32]),fmaxf(pp[lane+64],pp[lane+96]));
    m = warpMax(m);
    if(!lane) sF[36]=m;
  } else if(w==6){
    const float* pp = g_pA + 32*NBB;
    float s = pp[lane]+pp[lane+32]+pp[lane+64]+pp[lane+96];
    s = warpSum(s);
    if(!lane) sF[37]=s;
  } else if(w==7){
    const float* pp = g_pA + 33*NBB;
    float s = pp[lane]+pp[lane+32]+pp[lane+64]+pp[lane+96];
    s = warpSum(s);
    if(!lane) sF[38]=s;
  }
  __syncthreads();
  if(t<16){
    float m3 = sF[t]*INVN;
    float v3 = sF[16+t]*INVN - m3*m3;
    float is3 = rsqrtf(v3+EPSBN);
    sa3[t] = is3*gt[t];
    sb3[t] = betat[t] - m3*is3*gt[t];
    float mxy = sF[35]; if(mxy==0.f) mxy=1.f;
    float mxx = sF[36]; if(mxx==0.f) mxx=1.f;
    float Syy=sF[32]*INVN, Sxx=sF[33]*INVN, Sxy=sF[34]*INVN;
    float w0 = Wfc[t]/mxy;
    float w1 = Wfc[16+t]/mxx;
    float v2 = w0*w0*Syy + 2.f*w0*w1*Sxy + w1*w1*Sxx;
    float a2 = rsqrtf(v2+EPSBN)*gfc[t];
    su0[t]=w0*a2; su1[t]=w1*a2; sb2[t]=betafc[t];
  }
  if(t==16){ sc[0]=sF[37]*INVN; sc[1]=sF[38]*INVN; }
  __syncthreads();

  float gy=(float)qyi, gx=(float)qxi;
  float ry=gy-sc[0], rx=gx-sc[1];
  float q4[4];
  q4[0]=pv.x+ry*su0[4*r+0]+rx*su1[4*r+0]+sb2[4*r+0];
  q4[1]=pv.y+ry*su0[4*r+1]+rx*su1[4*r+1]+sb2[4*r+1];
  q4[2]=pv.z+ry*su0[4*r+2]+rx*su1[4*r+2]+sb2[4*r+2];
  q4[3]=pv.w+ry*su0[4*r+3]+rx*su1[4*r+3]+sb2[4*r+3];

  // thread r owns head r: 4 logits + 8 offsets
  float lg[4], offy[4], offx[4];
#pragma unroll
  for(int p=0;p<4;p++){
    lg[p]=sbattn[4*r+p];
    offy[p]=sboff[r*8+p*2];
    offx[p]=sboff[r*8+p*2+1];
  }
#pragma unroll
  for(int rr=0;rr<4;rr++){
    float qs[4];
#pragma unroll
    for(int k=0;k<4;k++) qs[k]=__shfl_sync(FULLM, q4[k], gbase+rr);
#pragma unroll
    for(int k=0;k<4;k++){
      int c = 4*rr+k;
#pragma unroll
      for(int p=0;p<4;p++){
        lg[p]  += qs[k]*sWattn[c*16 + 4*r + p];
        offy[p]+= qs[k]*sWoff[c*32 + r*8 + p*2];
        offx[p]+= qs[k]*sWoff[c*32 + r*8 + p*2+1];
      }
    }
  }
  float mx=fmaxf(fmaxf(lg[0],lg[1]),fmaxf(lg[2],lg[3]));
  float e0=expf(lg[0]-mx), e1=expf(lg[1]-mx), e2=expf(lg[2]-mx), e3=expf(lg[3]-mx);
  float inv=1.f/(e0+e1+e2+e3);
  lg[0]=e0*inv; lg[1]=e1*inv; lg[2]=e2*inv; lg[3]=e3*inv;

  float acc4[4]={0.f,0.f,0.f,0.f};
#define CORNER(Yf,Xf,Wgt) do{ \
    float _y=(Yf), _x=(Xf); \
    if(_y>=0.f && _y<=(float)(HH-1) && _x>=0.f && _x<=(float)(WW-1)){ \
      int _i = ((int)_y)*WW + (int)_x; \
      const float4 _v = *(const float4*)(g_val + _i*CC + 4*r); \
      float _w=(Wgt); \
      acc4[0]+=_w*_v.x; acc4[1]+=_w*_v.y; acc4[2]+=_w*_v.z; acc4[3]+=_w*_v.w; \
    } }while(0)
#pragma unroll
  for(int p=0;p<4;p++){
    float ly=gy+offy[p], lx=gx+offx[p];
    float fy=floorf(ly), fx=floorf(lx);
    float wy=ly-fy, wx=lx-fx;
    float ap=lg[p];
    CORNER(fy,     fx,     ap*(1.f-wy)*(1.f-wx));
    CORNER(fy,     fx+1.f, ap*(1.f-wy)*wx);
    CORNER(fy+1.f, fx,     ap*wy*(1.f-wx));
    CORNER(fy+1.f, fx+1.f, ap*wy*wx);
  }
#undef CORNER

  float img4[4];
#pragma unroll
  for(int j=0;j<4;j++) img4[j]=sbout[4*r+j];
#pragma unroll
  for(int rr=0;rr<4;rr++){
    float as[4];
#pragma unroll
    for(int k=0;k<4;k++) as[k]=__shfl_sync(FULLM, acc4[k], gbase+rr);
#pragma unroll
    for(int k=0;k<4;k++)
#pragma unroll
      for(int j=0;j<4;j++) img4[j] += as[k]*sWout[(4*rr+k)*16 + 4*r+j];
  }
  img4[0]+=nb.x; img4[1]+=nb.y; img4[2]+=nb.z; img4[3]+=nb.w;

  float pp4[4];
  pp4[0]=yv.x*sa3[4*r+0]+sb3[4*r+0];
  pp4[1]=yv.y*sa3[4*r+1]+sb3[4*r+1];
  pp4[2]=yv.z*sa3[4*r+2]+sb3[4*r+2];
  pp4[3]=yv.w*sa3[4*r+3]+sb3[4*r+3];

  float y4f[4];
#pragma unroll
  for(int j=0;j<4;j++) y4f[j]=sbf[4*r+j];
#pragma unroll
  for(int rr=0;rr<4;rr++){
    float ps[4], is_[4];
#pragma unroll
    for(int k=0;k<4;k++){
      ps[k] =__shfl_sync(FULLM, pp4[k],  gbase+rr);
      is_[k]=__shfl_sync(FULLM, img4[k], gbase+rr);
    }
#pragma unroll
    for(int k=0;k<4;k++){
      float pvv=fmaxf(ps[k],0.f), iv=fmaxf(is_[k],0.f);
#pragma unroll
      for(int j=0;j<4;j++)
        y4f[j] += pvv*sWf[(4*rr+k)*16 + 4*r+j] + iv*sWf[(16+4*rr+k)*16 + 4*r+j];
    }
  }
  {
    float s1[4], s2[4];
#pragma unroll
    for(int j=0;j<4;j++){ s1[j]=y4f[j]; s2[j]=y4f[j]*y4f[j]; }
#pragma unroll
    for(int o=4;o<32;o<<=1)
#pragma unroll
      for(int j=0;j<4;j++){
        s1[j]+=__shfl_down_sync(FULLM,s1[j],o);
        s2[j]+=__shfl_down_sync(FULLM,s2[j],o);
      }
    if(lane<4)
#pragma unroll
      for(int j=0;j<4;j++){ red[w][4*lane+j]=s1[j]; red[w][16+4*lane+j]=s2[j]; }
  }
  __syncthreads();
  if(t<32){
    float s=0.f;
#pragma unroll
    for(int k=0;k<NW;k++) s += red[k][t];
    g_p3[t*NBB+b]=s;
  }

  gbar(3);

  // ---- final BN + relu (y4f still in registers) ----
  for(int i=w;i<32;i+=NW){
    const float* pp = g_p3 + i*NBB;
    float s = pp[lane]+pp[lane+32]+pp[lane+64]+pp[lane+96];
    s = warpSum(s);
    if(!lane) sP[i]=s;
  }
  __syncthreads();
  if(t<16){
    float m = sP[t]*INVN;
    float vv = sP[16+t]*INVN - m*m;
    float is = rsqrtf(vv+EPSBN);
    a4[t]=is*gf[t];
    b4[t]=betaf[t] - m*is*gf[t];
  }
  __syncthreads();
  float4 ov;
  ov.x = fmaxf(y4f[0]*a4[4*r+0]+b4[4*r+0], 0.f);
  ov.y = fmaxf(y4f[1]*a4[4*r+1]+b4[4*r+1], 0.f);
  ov.z = fmaxf(y4f[2]*a4[4*r+2]+b4[4*r+2], 0.f);
  ov.w = fmaxf(y4f[3]*a4[4*r+3]+b4[4*r+3], 0.f);
  *(float4*)(out + n*CC + 4*r) = ov;
}

// ------------------------- launch ------------------------------------------
extern "C" void kernel_launch(void* const* d_in, const int* in_sizes, int n_in,
                              void* d_out, int out_size){
  const float* pf     = (const float*)d_in[0];
  const float* imf    = (const float*)d_in[1];
  const int*   grid   = (const int*)  d_in[2];
  const float* Wk     = (const float*)d_in[3];
  const float* bk     = (const float*)d_in[4];
  const float* gk     = (const float*)d_in[5];
  const float* betak  = (const float*)d_in[6];
  const float* Wfc    = (const float*)d_in[7];
  /* bfc = d_in[8] cancels analytically */
  const float* gfc    = (const float*)d_in[9];
  const float* betafc = (const float*)d_in[10];
  const float* Wt     = (const float*)d_in[11];
  const float* bt     = (const float*)d_in[12];
  const float* gt     = (const float*)d_in[13];
  const float* betat  = (const float*)d_in[14];
  const float* Woff   = (const float*)d_in[15];
  const float* boff   = (const float*)d_in[16];
  const float* Wattn  = (const float*)d_in[17];
  const float* battn  = (const float*)d_in[18];
  const float* Wval   = (const float*)d_in[19];
  const float* bval   = (const float*)d_in[20];
  const float* Wout   = (const float*)d_in[21];
  const float* bout   = (const float*)d_in[22];
  const float* Wf     = (const float*)d_in[23];
  const float* bf     = (const float*)d_in[24];
  const float* gf     = (const float*)d_in[25];
  const float* betaf  = (const float*)d_in[26];
  float* out = (float*)d_out;

  k_SS <<<NBB, NT>>>(pf, grid, Wk, bk, gk, betak, Wt, bt);
  k_knn<<<NPTS/4, 128>>>(grid, imf, Wval, bval);
  k_EG <<<NBB, NT>>>(grid, Wfc, gfc, betafc, gt, betat,
                     Woff, boff, Wattn, battn, Wout, bout, Wf, bf,
                     gf, betaf, out);
}

// round 16
// speedup vs baseline: 1.5428x; 1.0222x over previous
#include <cuda_runtime.h>

#define NPTS 16384
#define CC 16
#define HH 256
#define WW 704
#define HWIMG (HH*WW)        // 180224
#define EPSBN 1e-3f
#define NBB 128              // persistent SS blocks (wave-1 resident)
#define INITB 352            // init-role blocks (352*512 == HWIMG)
#define NT 512               // threads/block (4 threads per point)
#define NW 16                // warps/block
#define PPB 128              // points per block
#define INVN (1.0f/16384.0f)
#define NSX 44               // supercells per row (704/16)
#define NSC (HH*NSX)         // 11264 = 128*88
#define CHUNK 88
#define KNNR 10
#define KNNTH 120ULL
#define FULLM 0xffffffffu

// ------------------------- device scratch ----------------------------------
__device__ __align__(16) float g_val[HWIMG*CC];
__device__ __align__(16) float g_neigh[NPTS*CC];
__device__ __align__(16) float g_pts[NPTS*CC];
__device__ __align__(16) float g_Y3[NPTS*CC];
__device__ float g_pA[34*NBB];       // transposed: [item][block]
__device__ float g_p2[37*NBB];
__device__ float g_p3[32*NBB];
__device__ int g_cellCnt[NSC];       // zero-init; self-zeroing (scatter drains)
__device__ int g_cellStart[NSC+1];
__device__ int g_bs[NBB];
__device__ unsigned g_packed[NPTS];  // (idx<<18)|(y<<10)|x, grouped by supercell
__device__ int g_bc[4];              // phase barrier counters (self-resetting)

__device__ __forceinline__ float warpSum(float v){
#pragma unroll
  for(int o=16;o>0;o>>=1) v += __shfl_down_sync(FULLM, v, o);
  return v;
}
__device__ __forceinline__ int warpSumI(int v){
#pragma unroll
  for(int o=16;o>0;o>>=1) v += __shfl_down_sync(FULLM, v, o);
  return v;
}
__device__ __forceinline__ float warpMax(float v){
#pragma unroll
  for(int o=16;o>0;o>>=1) v = fmaxf(v, __shfl_down_sync(FULLM, v, o));
  return v;
}

// grid barrier across the NBB SS-role blocks only
__device__ __forceinline__ void gbar(int idx){
  __syncthreads();
  if(threadIdx.x==0){
    __threadfence();
    atomicAdd(&g_bc[idx], 1);
    while(((volatile int*)g_bc)[idx] < NBB) __nanosleep(32);
    __threadfence();
  }
  __syncthreads();
}

// ------------------------- K1: SS blocks + concurrent init blocks -----------
__global__ void __launch_bounds__(NT) k_SS(const float* __restrict__ pf,
    const int* __restrict__ grid,
    const float* __restrict__ Wk, const float* __restrict__ bk,
    const float* __restrict__ gk, const float* __restrict__ betak,
    const float* __restrict__ Wt, const float* __restrict__ bt,
    const float* __restrict__ imf,
    const float* __restrict__ Wval, const float* __restrict__ bval){
  __shared__ float sW[CC*CC];
  __shared__ float sb[CC];
  __shared__ float red[NW][37];
  __shared__ int sredI[NW];
  __shared__ float sA[34];
  __shared__ float sa1[CC], sb1[CC], scc[2];
  int b=blockIdx.x, t=threadIdx.x;

  // ================= init role: value table, no barriers ==================
  if(b >= NBB){
    for(int i=t;i<CC*CC;i+=NT) sW[i]=Wval[i];
    if(t<CC) sb[t]=bval[t];
    __syncthreads();
    int p = (b-NBB)*NT + t;
    float x[CC];
#pragma unroll
    for(int c=0;c<CC;c++) x[c] = __ldg(&imf[c*HWIMG + p]);
    float o[CC];
#pragma unroll
    for(int j=0;j<CC;j++){
      float s=sb[j];
#pragma unroll
      for(int c=0;c<CC;c++) s += x[c]*sW[c*CC+j];
      o[j]=s;
    }
    float4* dst = (float4*)(g_val + p*CC);
    dst[0]=make_float4(o[0],o[1],o[2],o[3]);
    dst[1]=make_float4(o[4],o[5],o[6],o[7]);
    dst[2]=make_float4(o[8],o[9],o[10],o[11]);
    dst[3]=make_float4(o[12],o[13],o[14],o[15]);
    return;
  }

  // ================= SS role ==============================================
  int lane=t&31, w=t>>5, r=t&3;
  int gbase = (lane&~3);

  // prefetch per-point data FIRST (hide latency behind smem staging)
  int n = b*PPB + (t>>2);
  int gyi = __ldg(&grid[2*n]), gxi = __ldg(&grid[2*n+1]);
  float4 xv = __ldg((const float4*)(pf + n*CC + 4*r));

  if(b==0 && t==0) *(volatile int*)&g_bc[3] = 0;
  for(int i=t;i<CC*CC;i+=NT) sW[i]=Wk[i];
  if(t<CC) sb[t]=bk[t];
  __syncthreads();

  // ---- P0: count + Y1 (4 threads/point; thread owns channels 4r..4r+3) ----
  if(r==0) atomicAdd(&g_cellCnt[gyi*NSX + (gxi>>4)], 1);
  float x4[4] = {xv.x, xv.y, xv.z, xv.w};
  float y4v[4];
#pragma unroll
  for(int j=0;j<4;j++) y4v[j]=sb[4*r+j];
#pragma unroll
  for(int rr=0;rr<4;rr++){
    float xs[4];
#pragma unroll
    for(int k=0;k<4;k++) xs[k]=__shfl_sync(FULLM, x4[k], gbase+rr);
#pragma unroll
    for(int k=0;k<4;k++)
#pragma unroll
      for(int j=0;j<4;j++) y4v[j] += xs[k]*sW[(4*rr+k)*CC + 4*r+j];
  }
  {
    float s1[4], s2[4];
#pragma unroll
    for(int j=0;j<4;j++){ s1[j]=y4v[j]; s2[j]=y4v[j]*y4v[j]; }
#pragma unroll
    for(int o=4;o<32;o<<=1)
#pragma unroll
      for(int j=0;j<4;j++){
        s1[j]+=__shfl_down_sync(FULLM,s1[j],o);
        s2[j]+=__shfl_down_sync(FULLM,s2[j],o);
      }
    if(lane<4)
#pragma unroll
      for(int j=0;j<4;j++){ red[w][4*lane+j]=s1[j]; red[w][16+4*lane+j]=s2[j]; }
    float gy=(r==0)?(float)gyi:0.f, gx=(r==0)?(float)gxi:0.f;
    float sgy=warpSum(gy), sgx=warpSum(gx);
    if(!lane){ red[w][32]=sgy; red[w][33]=sgx; }
  }
  __syncthreads();
  if(t<34){
    float s=0.f;
#pragma unroll
    for(int k=0;k<NW;k++) s += red[k][t];
    g_pA[t*NBB+b] = s;
  }
  gbar(0);

  // ---- P1: warp-0 scan of this block's 88 supercell counts ----
  int cbase = b*CHUNK;
  if(w==0){
    int base3 = lane*3;
    int loc[3]; int s=0;
#pragma unroll
    for(int i=0;i<3;i++){
      loc[i]=s;
      int idx=base3+i;
      if(idx<CHUNK) s += g_cellCnt[cbase+idx];
    }
    int incl=s;
#pragma unroll
    for(int o=1;o<32;o<<=1){ int xx=__shfl_up_sync(FULLM,incl,o); if(lane>=o) incl+=xx; }
    int pref = incl - s;
#pragma unroll
    for(int i=0;i<3;i++){
      int idx=base3+i;
      if(idx<CHUNK) g_cellStart[cbase+idx] = pref + loc[i];
    }
    if(lane==31) g_bs[b] = incl;
  }
  gbar(1);

  // ---- P2: add block offsets ----
  {
    int vb = (t<b) ? g_bs[t] : 0;
    int s = warpSumI(vb);
    if(!lane) sredI[w]=s;
    __syncthreads();
    int off=0;
#pragma unroll
    for(int k=0;k<NW;k++) off += sredI[k];
    if(t<CHUNK) g_cellStart[cbase+t] += off;
    if(b==0 && t==0) g_cellStart[NSC]=NPTS;
  }
  gbar(2);

  // ---- P3: stats finalize + scatter + pts/Y3 + p2 partials ----
  for(int i=w;i<34;i+=NW){
    const float* pp = g_pA + i*NBB;
    float s = pp[lane]+pp[lane+32]+pp[lane+64]+pp[lane+96];
    s = warpSum(s);
    if(!lane) sA[i]=s;
  }
  for(int i=t;i<CC*CC;i+=NT) sW[i]=Wt[i];
  if(t<CC) sb[t]=bt[t];
  __syncthreads();
  if(t<CC){
    float m = sA[t]*INVN;
    float vv = sA[16+t]*INVN - m*m;
    float is = rsqrtf(vv+EPSBN);
    sa1[t] = is*gk[t];
    sb1[t] = betak[t] - m*is*gk[t];
  }
  if(t==16) scc[0]=sA[32]*INVN;
  if(t==17) scc[1]=sA[33]*INVN;
  __syncthreads();
  if(r==0){
    int cid = gyi*NSX + (gxi>>4);
    int old = atomicSub(&g_cellCnt[cid], 1);   // drains to 0 (replay-safe)
    g_packed[g_cellStart[cid] + old - 1] =
        ((unsigned)n<<18) | ((unsigned)gyi<<10) | (unsigned)gxi;
  }
  float p4[4];
#pragma unroll
  for(int j=0;j<4;j++) p4[j] = y4v[j]*sa1[4*r+j] + sb1[4*r+j];
  *(float4*)(g_pts + n*CC + 4*r) = make_float4(p4[0],p4[1],p4[2],p4[3]);
  float y3[4];
#pragma unroll
  for(int j=0;j<4;j++) y3[j]=sb[4*r+j];
#pragma unroll
  for(int rr=0;rr<4;rr++){
    float xs[4];
#pragma unroll
    for(int k=0;k<4;k++) xs[k]=__shfl_sync(FULLM, p4[k], gbase+rr);
#pragma unroll
    for(int k=0;k<4;k++)
#pragma unroll
      for(int j=0;j<4;j++) y3[j] += xs[k]*sW[(4*rr+k)*CC + 4*r+j];
  }
  *(float4*)(g_Y3 + n*CC + 4*r) = make_float4(y3[0],y3[1],y3[2],y3[3]);
  {
    float s1[4], s2[4];
#pragma unroll
    for(int j=0;j<4;j++){ s1[j]=y3[j]; s2[j]=y3[j]*y3[j]; }
#pragma unroll
    for(int o=4;o<32;o<<=1)
#pragma unroll
      for(int j=0;j<4;j++){
        s1[j]+=__shfl_down_sync(FULLM,s1[j],o);
        s2[j]+=__shfl_down_sync(FULLM,s2[j],o);
      }
    if(lane<4)
#pragma unroll
      for(int j=0;j<4;j++){ red[w][4*lane+j]=s1[j]; red[w][16+4*lane+j]=s2[j]; }
    float ry=(float)gyi-scc[0], rx=(float)gxi-scc[1];
    float vyy=(r==0)?ry*ry:0.f, vxx=(r==0)?rx*rx:0.f, vxy=(r==0)?ry*rx:0.f;
    float myy=(r==0)?fabsf(ry):0.f, mxx2=(r==0)?fabsf(rx):0.f;
    float a_=warpSum(vyy); if(!lane) red[w][32]=a_;
    float b_=warpSum(vxx); if(!lane) red[w][33]=b_;
    float c_=warpSum(vxy); if(!lane) red[w][34]=c_;
    float d_=warpMax(myy); if(!lane) red[w][35]=d_;
    float e_=warpMax(mxx2); if(!lane) red[w][36]=e_;
  }
  __syncthreads();
  if(t<35){
    float s=0.f;
#pragma unroll
    for(int k=0;k<NW;k++) s += red[k][t];
    g_p2[t*NBB+b]=s;
  } else if(t<37){
    float m=0.f;
#pragma unroll
    for(int k=0;k<NW;k++) m = fmaxf(m, red[k][t]);
    g_p2[t*NBB+b]=m;
  }
}

// ------------------------- KNN helpers --------------------------------------
__device__ __forceinline__ unsigned long long umin64(unsigned long long a, unsigned long long b){
  return a<b ? a : b;
}
__device__ __forceinline__ unsigned long long umax64(unsigned long long a, unsigned long long b){
  return a<b ? b : a;
}
#define INS9(L0,L1,L2,L3,L4,L5,L6,L7,L8,KEY) do{ \
  unsigned long long _k=(KEY); \
  if(_k < L8){ \
    unsigned long long _t; \
    _t=L0; L0=umin64(_t,_k); _k=umax64(_t,_k); \
    _t=L1; L1=umin64(_t,_k); _k=umax64(_t,_k); \
    _t=L2; L2=umin64(_t,_k); _k=umax64(_t,_k); \
    _t=L3; L3=umin64(_t,_k); _k=umax64(_t,_k); \
    _t=L4; L4=umin64(_t,_k); _k=umax64(_t,_k); \
    _t=L5; L5=umin64(_t,_k); _k=umax64(_t,_k); \
    _t=L6; L6=umin64(_t,_k); _k=umax64(_t,_k); \
    _t=L7; L7=umin64(_t,_k); _k=umax64(_t,_k); \
    L8=umin64(L8,_k); \
  } }while(0)

__device__ __forceinline__ int isqrt_dev(int v){
  if(v < 0) return -1;
  int h = (int)sqrtf((float)v);
  while((h+1)*(h+1) <= v) h++;
  while(h>0 && h*h > v) h--;
  return h;
}

__device__ __forceinline__ unsigned long long mkkey(unsigned p, int qy, int qx){
  int dy = (int)((p>>10)&0xFFu) - qy;
  int dx = (int)(p&0x3FFu) - qx;
  return ((unsigned long long)(unsigned)(dy*dy+dx*dx) << 32) | p;
}

// ------------------------- K2: warp-per-query KNN + neighbor mean -----------
__global__ void __launch_bounds__(128) k_knn(const int* __restrict__ grid,
                                             const float* __restrict__ imf){
  int lane = threadIdx.x & 31;
  int n = blockIdx.x*4 + (threadIdx.x >> 5);
  int qy = __ldg(&grid[2*n]), qx = __ldg(&grid[2*n+1]);

  unsigned long long l0=~0ULL,l1=~0ULL,l2=~0ULL,l3=~0ULL,l4=~0ULL,
                     l5=~0ULL,l6=~0ULL,l7=~0ULL,l8=~0ULL;
  int row = qy - KNNR + lane;
  int s=0, e=0;
  if(lane < 2*KNNR+1 && row >= 0 && row < HH){
    int sxlo = max(qx-KNNR,0) >> 4;
    int sxhi = min(qx+KNNR,WW-1) >> 4;
    s = g_cellStart[row*NSX + sxlo];
    e = g_cellStart[row*NSX + sxhi + 1];
  }
  // software-pipelined candidate stream: prefetch next while inserting current
  unsigned nxt = (s<e) ? g_packed[s] : 0u;
  while(__any_sync(FULLM, s<e)){
    bool act = (s<e);
    unsigned cur = nxt;
    s++;
    if(s<e) nxt = g_packed[s];
    if(act){
      unsigned long long key = mkkey(cur, qy, qx);
      INS9(l0,l1,l2,l3,l4,l5,l6,l7,l8,key);
    }
  }
  unsigned long long w0,w1,w2,w3,w4,w5,w6,w7,w8;
#define ROUND(WR) { \
    unsigned long long m=l0; \
    _Pragma("unroll") \
    for(int o=16;o>0;o>>=1){ unsigned long long t2=__shfl_xor_sync(FULLM,m,o); if(t2<m)m=t2; } \
    WR = m; \
    if(l0==m){ l0=l1;l1=l2;l2=l3;l3=l4;l4=l5;l5=l6;l6=l7;l7=l8;l8=~0ULL; } }
  ROUND(w0) ROUND(w1) ROUND(w2) ROUND(w3) ROUND(w4)
  ROUND(w5) ROUND(w6) ROUND(w7) ROUND(w8)
#undef ROUND

  if(w8 == ~0ULL || (w8>>32) > KNNTH){
    unsigned long long f0=~0ULL,f1=~0ULL,f2=~0ULL,f3=~0ULL,f4=~0ULL,
                       f5=~0ULL,f6=~0ULL,f7=~0ULL,f8=~0ULL;
    if(lane==0){
      for(int d=0; d<HH; d++){
        if(f8 != ~0ULL && (unsigned long long)(d*d) > (f8>>32)) break;
        for(int sgn=0; sgn<2; sgn++){
          if(d==0 && sgn) break;
          int yy = sgn ? qy+d : qy-d;
          if((unsigned)yy >= HH) continue;
          int xlo=0, xhi=WW-1;
          if(f8 != ~0ULL){
            int vv = (int)(f8>>32) - d*d;
            if(vv < 0) continue;
            int hw = isqrt_dev(vv);
            xlo = max(qx-hw,0); xhi = min(qx+hw,WW-1);
          }
          int ss = g_cellStart[yy*NSX + (xlo>>4)];
          int ee = g_cellStart[yy*NSX + (xhi>>4) + 1];
          for(; ss<ee; ss++){
            unsigned long long key = mkkey(g_packed[ss], qy, qx);
            INS9(f0,f1,f2,f3,f4,f5,f6,f7,f8,key);
          }
        }
      }
    }
    w1=__shfl_sync(FULLM,f1,0); w2=__shfl_sync(FULLM,f2,0);
    w3=__shfl_sync(FULLM,f3,0); w4=__shfl_sync(FULLM,f4,0); w5=__shfl_sync(FULLM,f5,0);
    w6=__shfl_sync(FULLM,f6,0); w7=__shfl_sync(FULLM,f7,0); w8=__shfl_sync(FULLM,f8,0);
  }

  unsigned p1=(unsigned)w1, p2=(unsigned)w2, p3=(unsigned)w3, p4=(unsigned)w4,
           p5=(unsigned)w5, p6=(unsigned)w6, p7=(unsigned)w7, p8=(unsigned)w8;
#define POS(P) ((int)(((P)>>10)&0xFFu)*WW + (int)((P)&0x3FFu))
  int o1=POS(p1),o2=POS(p2),o3=POS(p3),o4=POS(p4),
      o5=POS(p5),o6=POS(p6),o7=POS(p7),o8=POS(p8);
#undef POS
  int ni = lane>>2;                 // neighbor group 0..7 -> winner ni+1
  int off = o1;
  off = (ni==1)?o2:off; off = (ni==2)?o3:off; off = (ni==3)?o4:off;
  off = (ni==4)?o5:off; off = (ni==5)?o6:off; off = (ni==6)?o7:off;
  off = (ni==7)?o8:off;
  const float* base = imf + (lane&3)*4*HWIMG + off;
  float4 v;
  v.x = __ldg(base + 0*HWIMG);
  v.y = __ldg(base + 1*HWIMG);
  v.z = __ldg(base + 2*HWIMG);
  v.w = __ldg(base + 3*HWIMG);
#pragma unroll
  for(int o=4;o<=16;o<<=1){
    v.x += __shfl_xor_sync(FULLM, v.x, o);
    v.y += __shfl_xor_sync(FULLM, v.y, o);
    v.z += __shfl_xor_sync(FULLM, v.z, o);
    v.w += __shfl_xor_sync(FULLM, v.w, o);
  }
  if(lane < 4){
    v.x*=0.125f; v.y*=0.125f; v.z*=0.125f; v.w*=0.125f;
    ((float4*)(g_neigh + n*CC))[lane] = v;
  }
}

// ------------------------- K3: deform attn + fuse + final BN (4 thr/point) --
__global__ void __launch_bounds__(NT) k_EG(const int* __restrict__ grid,
    const float* __restrict__ Wfc, const float* __restrict__ gfc, const float* __restrict__ betafc,
    const float* __restrict__ gt,  const float* __restrict__ betat,
    const float* __restrict__ Woff,const float* __restrict__ boff,
    const float* __restrict__ Wattn,const float* __restrict__ battn,
    const float* __restrict__ Wout,const float* __restrict__ bout,
    const float* __restrict__ Wf,  const float* __restrict__ bf,
    const float* __restrict__ gf,  const float* __restrict__ betaf,
    float* __restrict__ out){
  __shared__ float sF[40];
  __shared__ float sWoff[CC*32], sWattn[CC*16], sWout[CC*16], sWf[32*CC];
  __shared__ float sboff[32], sbattn[16], sbout[16], sbf[16];
  __shared__ float sa3[16], sb3[16], su0[16], su1[16], sb2[16], sc[2];
  __shared__ float red[NW][32];
  __shared__ float sP[32], a4[16], b4[16];
  int b=blockIdx.x, t=threadIdx.x;
  int lane=t&31, w=t>>5, r=t&3;
  int gbase = (lane&~3);

  // prefetch per-point data FIRST (hide latency behind smem staging + prologue)
  int n = b*PPB + (t>>2);
  int qyi = __ldg(&grid[2*n]), qxi = __ldg(&grid[2*n+1]);
  float4 pv = __ldg((const float4*)(g_pts + n*CC + 4*r));
  float4 yv = __ldg((const float4*)(g_Y3 + n*CC + 4*r));
  float4 nb = __ldg((const float4*)(g_neigh + n*CC + 4*r));

  if(b==0 && t==0){
    *(volatile int*)&g_bc[0]=0;
    *(volatile int*)&g_bc[1]=0;
    *(volatile int*)&g_bc[2]=0;
  }
  for(int i=t;i<CC*32;i+=NT) sWoff[i]=Woff[i];
  for(int i=t;i<CC*16;i+=NT){ sWattn[i]=Wattn[i]; sWout[i]=Wout[i]; }
  for(int i=t;i<32*CC;i+=NT) sWf[i]=Wf[i];
  if(t<32) sboff[t]=boff[t];
  if(t<16){ sbattn[t]=battn[t]; sbout[t]=bout[t]; sbf[t]=bf[t]; }
  for(int i=w;i<35;i+=NW){
    const float* pp = g_p2 + i*NBB;
    float s = pp[lane]+pp[lane+32]+pp[lane+64]+pp[lane+96];
    s = warpSum(s);
    if(!lane) sF[i]=s;
  }
  if(w==4){
    const float* pp = g_p2 + 35*NBB;
    float m = fmaxf(fmaxf(pp[lane],pp[lane+32]),fmaxf(pp[lane+64],pp[lane+96]));
    m = warpMax(m);
    if(!lane) sF[35]=m;
  } else if(w==5){
    const float* pp = g_p2 + 36*NBB;
    float m = fmaxf(fmaxf(pp[lane],pp[lane+32]),fmaxf(pp[lane+64],pp[lane+96]));
    m = warpMax(m);
    if(!lane) sF[36]=m;
  } else if(w==6){
    const float* pp = g_pA + 32*NBB;
    float s = pp[lane]+pp[lane+32]+pp[lane+64]+pp[lane+96];
    s = warpSum(s);
    if(!lane) sF[37]=s;
  } else if(w==7){
    const float* pp = g_pA + 33*NBB;
    float s = pp[lane]+pp[lane+32]+pp[lane+64]+pp[lane+96];
    s = warpSum(s);
    if(!lane) sF[38]=s;
  }
  __syncthreads();
  if(t<16){
    float m3 = sF[t]*INVN;
    float v3 = sF[16+t]*INVN - m3*m3;
    float is3 = rsqrtf(v3+EPSBN);
    sa3[t] = is3*gt[t];
    sb3[t] = betat[t] - m3*is3*gt[t];
    float mxy = sF[35]; if(mxy==0.f) mxy=1.f;
    float mxx = sF[36]; if(mxx==0.f) mxx=1.f;
    float Syy=sF[32]*INVN, Sxx=sF[33]*INVN, Sxy=sF[34]*INVN;
    float w0 = Wfc[t]/mxy;
    float w1 = Wfc[16+t]/mxx;
    float v2 = w0*w0*Syy + 2.f*w0*w1*Sxy + w1*w1*Sxx;
    float a2 = rsqrtf(v2+EPSBN)*gfc[t];
    su0[t]=w0*a2; su1[t]=w1*a2; sb2[t]=betafc[t];
  }
  if(t==16){ sc[0]=sF[37]*INVN; sc[1]=sF[38]*INVN; }
  __syncthreads();

  float gy=(float)qyi, gx=(float)qxi;
  float ry=gy-sc[0], rx=gx-sc[1];
  float q4[4];
  q4[0]=pv.x+ry*su0[4*r+0]+rx*su1[4*r+0]+sb2[4*r+0];
  q4[1]=pv.y+ry*su0[4*r+1]+rx*su1[4*r+1]+sb2[4*r+1];
  q4[2]=pv.z+ry*su0[4*r+2]+rx*su1[4*r+2]+sb2[4*r+2];
  q4[3]=pv.w+ry*su0[4*r+3]+rx*su1[4*r+3]+sb2[4*r+3];

  // thread r owns head r: 4 logits + 8 offsets
  float lg[4], offy[4], offx[4];
#pragma unroll
  for(int p=0;p<4;p++){
    lg[p]=sbattn[4*r+p];
    offy[p]=sboff[r*8+p*2];
    offx[p]=sboff[r*8+p*2+1];
  }
#pragma unroll
  for(int rr=0;rr<4;rr++){
    float qs[4];
#pragma unroll
    for(int k=0;k<4;k++) qs[k]=__shfl_sync(FULLM, q4[k], gbase+rr);
#pragma unroll
    for(int k=0;k<4;k++){
      int c = 4*rr+k;
#pragma unroll
      for(int p=0;p<4;p++){
        lg[p]  += qs[k]*sWattn[c*16 + 4*r + p];
        offy[p]+= qs[k]*sWoff[c*32 + r*8 + p*2];
        offx[p]+= qs[k]*sWoff[c*32 + r*8 + p*2+1];
      }
    }
  }
  float mx=fmaxf(fmaxf(lg[0],lg[1]),fmaxf(lg[2],lg[3]));
  float e0=expf(lg[0]-mx), e1=expf(lg[1]-mx), e2=expf(lg[2]-mx), e3=expf(lg[3]-mx);
  float inv=1.f/(e0+e1+e2+e3);
  lg[0]=e0*inv; lg[1]=e1*inv; lg[2]=e2*inv; lg[3]=e3*inv;

  float acc4[4]={0.f,0.f,0.f,0.f};
#define CORNER(Yf,Xf,Wgt) do{ \
    float _y=(Yf), _x=(Xf); \
    if(_y>=0.f && _y<=(float)(HH-1) && _x>=0.f && _x<=(float)(WW-1)){ \
      int _i = ((int)_y)*WW + (int)_x; \
      const float4 _v = *(const float4*)(g_val + _i*CC + 4*r); \
      float _w=(Wgt); \
      acc4[0]+=_w*_v.x; acc4[1]+=_w*_v.y; acc4[2]+=_w*_v.z; acc4[3]+=_w*_v.w; \
    } }while(0)
#pragma unroll
  for(int p=0;p<4;p++){
    float ly=gy+offy[p], lx=gx+offx[p];
    float fy=floorf(ly), fx=floorf(lx);
    float wy=ly-fy, wx=lx-fx;
    float ap=lg[p];
    CORNER(fy,     fx,     ap*(1.f-wy)*(1.f-wx));
    CORNER(fy,     fx+1.f, ap*(1.f-wy)*wx);
    CORNER(fy+1.f, fx,     ap*wy*(1.f-wx));
    CORNER(fy+1.f, fx+1.f, ap*wy*wx);
  }
#undef CORNER

  float img4[4];
#pragma unroll
  for(int j=0;j<4;j++) img4[j]=sbout[4*r+j];
#pragma unroll
  for(int rr=0;rr<4;rr++){
    float as[4];
#pragma unroll
    for(int k=0;k<4;k++) as[k]=__shfl_sync(FULLM, acc4[k], gbase+rr);
#pragma unroll
    for(int k=0;k<4;k++)
#pragma unroll
      for(int j=0;j<4;j++) img4[j] += as[k]*sWout[(4*rr+k)*16 + 4*r+j];
  }
  img4[0]+=nb.x; img4[1]+=nb.y; img4[2]+=nb.z; img4[3]+=nb.w;

  float pp4[4];
  pp4[0]=yv.x*sa3[4*r+0]+sb3[4*r+0];
  pp4[1]=yv.y*sa3[4*r+1]+sb3[4*r+1];
  pp4[2]=yv.z*sa3[4*r+2]+sb3[4*r+2];
  pp4[3]=yv.w*sa3[4*r+3]+sb3[4*r+3];

  float y4f[4];
#pragma unroll
  for(int j=0;j<4;j++) y4f[j]=sbf[4*r+j];
#pragma unroll
  for(int rr=0;rr<4;rr++){
    float ps[4], is_[4];
#pragma unroll
    for(int k=0;k<4;k++){
      ps[k] =__shfl_sync(FULLM, pp4[k],  gbase+rr);
      is_[k]=__shfl_sync(FULLM, img4[k], gbase+rr);
    }
#pragma unroll
    for(int k=0;k<4;k++){
      float pvv=fmaxf(ps[k],0.f), iv=fmaxf(is_[k],0.f);
#pragma unroll
      for(int j=0;j<4;j++)
        y4f[j] += pvv*sWf[(4*rr+k)*16 + 4*r+j] + iv*sWf[(16+4*rr+k)*16 + 4*r+j];
    }
  }
  {
    float s1[4], s2[4];
#pragma unroll
    for(int j=0;j<4;j++){ s1[j]=y4f[j]; s2[j]=y4f[j]*y4f[j]; }
#pragma unroll
    for(int o=4;o<32;o<<=1)
#pragma unroll
      for(int j=0;j<4;j++){
        s1[j]+=__shfl_down_sync(FULLM,s1[j],o);
        s2[j]+=__shfl_down_sync(FULLM,s2[j],o);
      }
    if(lane<4)
#pragma unroll
      for(int j=0;j<4;j++){ red[w][4*lane+j]=s1[j]; red[w][16+4*lane+j]=s2[j]; }
  }
  __syncthreads();
  if(t<32){
    float s=0.f;
#pragma unroll
    for(int k=0;k<NW;k++) s += red[k][t];
    g_p3[t*NBB+b]=s;
  }

  gbar(3);

  // ---- final BN + relu (y4f still in registers) ----
  for(int i=w;i<32;i+=NW){
    const float* pp = g_p3 + i*NBB;
    float s = pp[lane]+pp[lane+32]+pp[lane+64]+pp[lane+96];
    s = warpSum(s);
    if(!lane) sP[i]=s;
  }
  __syncthreads();
  if(t<16){
    float m = sP[t]*INVN;
    float vv = sP[16+t]*INVN - m*m;
    float is = rsqrtf(vv+EPSBN);
    a4[t]=is*gf[t];
    b4[t]=betaf[t] - m*is*gf[t];
  }
  __syncthreads();
  float4 ov;
  ov.x = fmaxf(y4f[0]*a4[4*r+0]+b4[4*r+0], 0.f);
  ov.y = fmaxf(y4f[1]*a4[4*r+1]+b4[4*r+1], 0.f);
  ov.z = fmaxf(y4f[2]*a4[4*r+2]+b4[4*r+2], 0.f);
  ov.w = fmaxf(y4f[3]*a4[4*r+3]+b4[4*r+3], 0.f);
  *(float4*)(out + n*CC + 4*r) = ov;
}

// ------------------------- launch ------------------------------------------
extern "C" void kernel_launch(void* const* d_in, const int* in_sizes, int n_in,
                              void* d_out, int out_size){
  const float* pf     = (const float*)d_in[0];
  const float* imf    = (const float*)d_in[1];
  const int*   grid   = (const int*)  d_in[2];
  const float* Wk     = (const float*)d_in[3];
  const float* bk     = (const float*)d_in[4];
  const float* gk     = (const float*)d_in[5];
  const float* betak  = (const float*)d_in[6];
  const float* Wfc    = (const float*)d_in[7];
  /* bfc = d_in[8] cancels analytically */
  const float* gfc    = (const float*)d_in[9];
  const float* betafc = (const float*)d_in[10];
  const float* Wt     = (const float*)d_in[11];
  const float* bt     = (const float*)d_in[12];
  const float* gt     = (const float*)d_in[13];
  const float* betat  = (const float*)d_in[14];
  const float* Woff   = (const float*)d_in[15];
  const float* boff   = (const float*)d_in[16];
  const float* Wattn  = (const float*)d_in[17];
  const float* battn  = (const float*)d_in[18];
  const float* Wval   = (const float*)d_in[19];
  const float* bval   = (const float*)d_in[20];
  const float* Wout   = (const float*)d_in[21];
  const float* bout   = (const float*)d_in[22];
  const float* Wf     = (const float*)d_in[23];
  const float* bf     = (const float*)d_in[24];
  const float* gf     = (const float*)d_in[25];
  const float* betaf  = (const float*)d_in[26];
  float* out = (float*)d_out;

  k_SS <<<NBB+INITB, NT>>>(pf, grid, Wk, bk, gk, betak, Wt, bt, imf, Wval, bval);
  k_knn<<<NPTS/4, 128>>>(grid, imf);
  k_EG <<<NBB, NT>>>(grid, Wfc, gfc, betafc, gt, betat,
                     Woff, boff, Wattn, battn, Wout, bout, Wf, bf,
                     gf, betaf, out);
}

// round 17
// speedup vs baseline: 1.8110x; 1.1739x over previous
#include <cuda_runtime.h>

#define NPTS 16384
#define CC 16
#define HH 256
#define WW 704
#define HWIMG (HH*WW)        // 180224
#define EPSBN 1e-3f
#define NBB 128              // persistent SS blocks (wave-1 resident)
#define INITB 352            // init-role blocks (352*512 == HWIMG)
#define NT 512               // threads/block (4 threads per point)
#define NW 16                // warps/block
#define PPB 128              // points per block
#define INVN (1.0f/16384.0f)
#define NSX 44               // supercells per row (704/16)
#define NSC (HH*NSX)         // 11264 = 128*88
#define CHUNK 88
#define KNNR 10
#define KNNTH 120u
#define FULLM 0xffffffffu
#define INVKEY 0xffffffffu

// ------------------------- device scratch ----------------------------------
__device__ __align__(16) float g_val[HWIMG*CC];
__device__ __align__(16) float g_neigh[NPTS*CC];
__device__ __align__(16) float g_pts[NPTS*CC];
__device__ __align__(16) float g_Y3[NPTS*CC];
__device__ float g_pA[34*NBB];       // transposed: [item][block]
__device__ float g_p2[37*NBB];
__device__ float g_p3[32*NBB];
__device__ int g_cellCnt[NSC];       // zero-init; self-zeroing (scatter drains)
__device__ int g_cellStart[NSC+1];
__device__ int g_bs[NBB];
__device__ unsigned g_packed[NPTS];  // (idx<<18)|(y<<10)|x, grouped by supercell
__device__ int g_bc[4];              // phase barrier counters (self-resetting)

__device__ __forceinline__ float warpSum(float v){
#pragma unroll
  for(int o=16;o>0;o>>=1) v += __shfl_down_sync(FULLM, v, o);
  return v;
}
__device__ __forceinline__ int warpSumI(int v){
#pragma unroll
  for(int o=16;o>0;o>>=1) v += __shfl_down_sync(FULLM, v, o);
  return v;
}
__device__ __forceinline__ float warpMax(float v){
#pragma unroll
  for(int o=16;o>0;o>>=1) v = fmaxf(v, __shfl_down_sync(FULLM, v, o));
  return v;
}

// grid barrier across the NBB SS-role blocks only
__device__ __forceinline__ void gbar(int idx){
  __syncthreads();
  if(threadIdx.x==0){
    __threadfence();
    atomicAdd(&g_bc[idx], 1);
    while(((volatile int*)g_bc)[idx] < NBB) __nanosleep(32);
    __threadfence();
  }
  __syncthreads();
}

// ------------------------- K1: SS blocks + concurrent init blocks -----------
__global__ void __launch_bounds__(NT) k_SS(const float* __restrict__ pf,
    const int* __restrict__ grid,
    const float* __restrict__ Wk, const float* __restrict__ bk,
    const float* __restrict__ gk, const float* __restrict__ betak,
    const float* __restrict__ Wt, const float* __restrict__ bt,
    const float* __restrict__ imf,
    const float* __restrict__ Wval, const float* __restrict__ bval){
  __shared__ float sW[CC*CC];
  __shared__ float sb[CC];
  __shared__ float red[NW][37];
  __shared__ int sredI[NW];
  __shared__ float sA[34];
  __shared__ float sa1[CC], sb1[CC], scc[2];
  int b=blockIdx.x, t=threadIdx.x;

  // ================= init role: value table, no barriers ==================
  if(b >= NBB){
    for(int i=t;i<CC*CC;i+=NT) sW[i]=Wval[i];
    if(t<CC) sb[t]=bval[t];
    __syncthreads();
    int p = (b-NBB)*NT + t;
    float x[CC];
#pragma unroll
    for(int c=0;c<CC;c++) x[c] = __ldg(&imf[c*HWIMG + p]);
    float o[CC];
#pragma unroll
    for(int j=0;j<CC;j++){
      float s=sb[j];
#pragma unroll
      for(int c=0;c<CC;c++) s += x[c]*sW[c*CC+j];
      o[j]=s;
    }
    float4* dst = (float4*)(g_val + p*CC);
    dst[0]=make_float4(o[0],o[1],o[2],o[3]);
    dst[1]=make_float4(o[4],o[5],o[6],o[7]);
    dst[2]=make_float4(o[8],o[9],o[10],o[11]);
    dst[3]=make_float4(o[12],o[13],o[14],o[15]);
    return;
  }

  // ================= SS role ==============================================
  int lane=t&31, w=t>>5, r=t&3;
  int gbase = (lane&~3);

  // prefetch per-point data FIRST (hide latency behind smem staging)
  int n = b*PPB + (t>>2);
  int gyi = __ldg(&grid[2*n]), gxi = __ldg(&grid[2*n+1]);
  float4 xv = __ldg((const float4*)(pf + n*CC + 4*r));

  if(b==0 && t==0) *(volatile int*)&g_bc[3] = 0;
  for(int i=t;i<CC*CC;i+=NT) sW[i]=Wk[i];
  if(t<CC) sb[t]=bk[t];
  __syncthreads();

  // ---- P0: count + Y1 (4 threads/point; thread owns channels 4r..4r+3) ----
  if(r==0) atomicAdd(&g_cellCnt[gyi*NSX + (gxi>>4)], 1);
  float x4[4] = {xv.x, xv.y, xv.z, xv.w};
  float y4v[4];
#pragma unroll
  for(int j=0;j<4;j++) y4v[j]=sb[4*r+j];
#pragma unroll
  for(int rr=0;rr<4;rr++){
    float xs[4];
#pragma unroll
    for(int k=0;k<4;k++) xs[k]=__shfl_sync(FULLM, x4[k], gbase+rr);
#pragma unroll
    for(int k=0;k<4;k++)
#pragma unroll
      for(int j=0;j<4;j++) y4v[j] += xs[k]*sW[(4*rr+k)*CC + 4*r+j];
  }
  {
    float s1[4], s2[4];
#pragma unroll
    for(int j=0;j<4;j++){ s1[j]=y4v[j]; s2[j]=y4v[j]*y4v[j]; }
#pragma unroll
    for(int o=4;o<32;o<<=1)
#pragma unroll
      for(int j=0;j<4;j++){
        s1[j]+=__shfl_down_sync(FULLM,s1[j],o);
        s2[j]+=__shfl_down_sync(FULLM,s2[j],o);
      }
    if(lane<4)
#pragma unroll
      for(int j=0;j<4;j++){ red[w][4*lane+j]=s1[j]; red[w][16+4*lane+j]=s2[j]; }
    float gy=(r==0)?(float)gyi:0.f, gx=(r==0)?(float)gxi:0.f;
    float sgy=warpSum(gy), sgx=warpSum(gx);
    if(!lane){ red[w][32]=sgy; red[w][33]=sgx; }
  }
  __syncthreads();
  if(t<34){
    float s=0.f;
#pragma unroll
    for(int k=0;k<NW;k++) s += red[k][t];
    g_pA[t*NBB+b] = s;
  }
  gbar(0);

  // ---- P1: warp-0 scan of this block's 88 supercell counts ----
  int cbase = b*CHUNK;
  if(w==0){
    int base3 = lane*3;
    int loc[3]; int s=0;
#pragma unroll
    for(int i=0;i<3;i++){
      loc[i]=s;
      int idx=base3+i;
      if(idx<CHUNK) s += g_cellCnt[cbase+idx];
    }
    int incl=s;
#pragma unroll
    for(int o=1;o<32;o<<=1){ int xx=__shfl_up_sync(FULLM,incl,o); if(lane>=o) incl+=xx; }
    int pref = incl - s;
#pragma unroll
    for(int i=0;i<3;i++){
      int idx=base3+i;
      if(idx<CHUNK) g_cellStart[cbase+idx] = pref + loc[i];
    }
    if(lane==31) g_bs[b] = incl;
  }
  gbar(1);

  // ---- P2: add block offsets ----
  {
    int vb = (t<b) ? g_bs[t] : 0;
    int s = warpSumI(vb);
    if(!lane) sredI[w]=s;
    __syncthreads();
    int off=0;
#pragma unroll
    for(int k=0;k<NW;k++) off += sredI[k];
    if(t<CHUNK) g_cellStart[cbase+t] += off;
    if(b==0 && t==0) g_cellStart[NSC]=NPTS;
  }
  gbar(2);

  // ---- P3: stats finalize + scatter + pts/Y3 + p2 partials ----
  for(int i=w;i<34;i+=NW){
    const float* pp = g_pA + i*NBB;
    float s = pp[lane]+pp[lane+32]+pp[lane+64]+pp[lane+96];
    s = warpSum(s);
    if(!lane) sA[i]=s;
  }
  for(int i=t;i<CC*CC;i+=NT) sW[i]=Wt[i];
  if(t<CC) sb[t]=bt[t];
  __syncthreads();
  if(t<CC){
    float m = sA[t]*INVN;
    float vv = sA[16+t]*INVN - m*m;
    float is = rsqrtf(vv+EPSBN);
    sa1[t] = is*gk[t];
    sb1[t] = betak[t] - m*is*gk[t];
  }
  if(t==16) scc[0]=sA[32]*INVN;
  if(t==17) scc[1]=sA[33]*INVN;
  __syncthreads();
  if(r==0){
    int cid = gyi*NSX + (gxi>>4);
    int old = atomicSub(&g_cellCnt[cid], 1);   // drains to 0 (replay-safe)
    g_packed[g_cellStart[cid] + old - 1] =
        ((unsigned)n<<18) | ((unsigned)gyi<<10) | (unsigned)gxi;
  }
  float p4[4];
#pragma unroll
  for(int j=0;j<4;j++) p4[j] = y4v[j]*sa1[4*r+j] + sb1[4*r+j];
  *(float4*)(g_pts + n*CC + 4*r) = make_float4(p4[0],p4[1],p4[2],p4[3]);
  float y3[4];
#pragma unroll
  for(int j=0;j<4;j++) y3[j]=sb[4*r+j];
#pragma unroll
  for(int rr=0;rr<4;rr++){
    float xs[4];
#pragma unroll
    for(int k=0;k<4;k++) xs[k]=__shfl_sync(FULLM, p4[k], gbase+rr);
#pragma unroll
    for(int k=0;k<4;k++)
#pragma unroll
      for(int j=0;j<4;j++) y3[j] += xs[k]*sW[(4*rr+k)*CC + 4*r+j];
  }
  *(float4*)(g_Y3 + n*CC + 4*r) = make_float4(y3[0],y3[1],y3[2],y3[3]);
  {
    float s1[4], s2[4];
#pragma unroll
    for(int j=0;j<4;j++){ s1[j]=y3[j]; s2[j]=y3[j]*y3[j]; }
#pragma unroll
    for(int o=4;o<32;o<<=1)
#pragma unroll
      for(int j=0;j<4;j++){
        s1[j]+=__shfl_down_sync(FULLM,s1[j],o);
        s2[j]+=__shfl_down_sync(FULLM,s2[j],o);
      }
    if(lane<4)
#pragma unroll
      for(int j=0;j<4;j++){ red[w][4*lane+j]=s1[j]; red[w][16+4*lane+j]=s2[j]; }
    float ry=(float)gyi-scc[0], rx=(float)gxi-scc[1];
    float vyy=(r==0)?ry*ry:0.f, vxx=(r==0)?rx*rx:0.f, vxy=(r==0)?ry*rx:0.f;
    float myy=(r==0)?fabsf(ry):0.f, mxx2=(r==0)?fabsf(rx):0.f;
    float a_=warpSum(vyy); if(!lane) red[w][32]=a_;
    float b_=warpSum(vxx); if(!lane) red[w][33]=b_;
    float c_=warpSum(vxy); if(!lane) red[w][34]=c_;
    float d_=warpMax(myy); if(!lane) red[w][35]=d_;
    float e_=warpMax(mxx2); if(!lane) red[w][36]=e_;
  }
  __syncthreads();
  if(t<35){
    float s=0.f;
#pragma unroll
    for(int k=0;k<NW;k++) s += red[k][t];
    g_p2[t*NBB+b]=s;
  } else if(t<37){
    float m=0.f;
#pragma unroll
    for(int k=0;k<NW;k++) m = fmaxf(m, red[k][t]);
    g_p2[t*NBB+b]=m;
  }
}

// ------------------------- KNN helpers --------------------------------------
// 32-bit key sorted insert (IMNMX ops)
#define INS9U(L0,L1,L2,L3,L4,L5,L6,L7,L8,KEY) do{ \
  unsigned _k=(KEY); \
  if(_k < L8){ \
    unsigned _t; \
    _t=L0; L0=min(_t,_k); _k=max(_t,_k); \
    _t=L1; L1=min(_t,_k); _k=max(_t,_k); \
    _t=L2; L2=min(_t,_k); _k=max(_t,_k); \
    _t=L3; L3=min(_t,_k); _k=max(_t,_k); \
    _t=L4; L4=min(_t,_k); _k=max(_t,_k); \
    _t=L5; L5=min(_t,_k); _k=max(_t,_k); \
    _t=L6; L6=min(_t,_k); _k=max(_t,_k); \
    _t=L7; L7=min(_t,_k); _k=max(_t,_k); \
    L8=min(L8,_k); \
  } }while(0)

// 64-bit variant for the rare exact fallback
__device__ __forceinline__ unsigned long long umin64(unsigned long long a, unsigned long long b){
  return a<b ? a : b;
}
__device__ __forceinline__ unsigned long long umax64(unsigned long long a, unsigned long long b){
  return a<b ? b : a;
}
#define INS9(L0,L1,L2,L3,L4,L5,L6,L7,L8,KEY) do{ \
  unsigned long long _k=(KEY); \
  if(_k < L8){ \
    unsigned long long _t; \
    _t=L0; L0=umin64(_t,_k); _k=umax64(_t,_k); \
    _t=L1; L1=umin64(_t,_k); _k=umax64(_t,_k); \
    _t=L2; L2=umin64(_t,_k); _k=umax64(_t,_k); \
    _t=L3; L3=umin64(_t,_k); _k=umax64(_t,_k); \
    _t=L4; L4=umin64(_t,_k); _k=umax64(_t,_k); \
    _t=L5; L5=umin64(_t,_k); _k=umax64(_t,_k); \
    _t=L6; L6=umin64(_t,_k); _k=umax64(_t,_k); \
    _t=L7; L7=umin64(_t,_k); _k=umax64(_t,_k); \
    L8=umin64(L8,_k); \
  } }while(0)

__device__ __forceinline__ int isqrt_dev(int v){
  if(v < 0) return -1;
  int h = (int)sqrtf((float)v);
  while((h+1)*(h+1) <= v) h++;
  while(h>0 && h*h > v) h--;
  return h;
}

// 32-bit key: (d2<<14) | idx  — valid while d2 < 2^18 (window path: d2<=200)
__device__ __forceinline__ unsigned mkkey32(unsigned p, int qy, int qx){
  int dy = (int)((p>>10)&0xFFu) - qy;
  int dx = (int)(p&0x3FFu) - qx;
  return ((unsigned)(dy*dy+dx*dx) << 14) | (p >> 18);
}
__device__ __forceinline__ unsigned long long mkkey64(unsigned p, int qy, int qx){
  int dy = (int)((p>>10)&0xFFu) - qy;
  int dx = (int)(p&0x3FFu) - qx;
  return ((unsigned long long)(unsigned)(dy*dy+dx*dx) << 32) | p;
}

// ------------------------- K2: warp-per-query KNN + neighbor mean -----------
__global__ void __launch_bounds__(128) k_knn(const int* __restrict__ grid,
                                             const float* __restrict__ imf){
  int lane = threadIdx.x & 31;
  int n = blockIdx.x*4 + (threadIdx.x >> 5);
  int qy = __ldg(&grid[2*n]), qx = __ldg(&grid[2*n+1]);

  unsigned l0=INVKEY,l1=INVKEY,l2=INVKEY,l3=INVKEY,l4=INVKEY,
           l5=INVKEY,l6=INVKEY,l7=INVKEY,l8=INVKEY;
  int row = qy - KNNR + lane;
  int s=0, e=0;
  if(lane < 2*KNNR+1 && row >= 0 && row < HH){
    int sxlo = max(qx-KNNR,0) >> 4;
    int sxhi = min(qx+KNNR,WW-1) >> 4;
    s = g_cellStart[row*NSX + sxlo];
    e = g_cellStart[row*NSX + sxhi + 1];
  }
  // software-pipelined candidate stream: prefetch next while inserting current
  unsigned nxt = (s<e) ? g_packed[s] : 0u;
  while(__any_sync(FULLM, s<e)){
    bool act = (s<e);
    unsigned cur = nxt;
    s++;
    if(s<e) nxt = g_packed[s];
    if(act){
      unsigned key = mkkey32(cur, qy, qx);
      INS9U(l0,l1,l2,l3,l4,l5,l6,l7,l8,key);
    }
  }
  // 9-round warp merge via REDUX.MIN.U32
  unsigned w8;
  int j1,j2,j3,j4,j5,j6,j7,j8;
#define ROUND32(DST) { \
    unsigned m = __reduce_min_sync(FULLM, l0); \
    DST; \
    if(l0==m){ l0=l1;l1=l2;l2=l3;l3=l4;l4=l5;l5=l6;l6=l7;l7=l8;l8=INVKEY; } }
  { unsigned dum;
    ROUND32(dum=m)           // rank 0 (lexicographic min) dropped
    ROUND32(j1=(int)(m&0x3FFFu))
    ROUND32(j2=(int)(m&0x3FFFu))
    ROUND32(j3=(int)(m&0x3FFFu))
    ROUND32(j4=(int)(m&0x3FFFu))
    ROUND32(j5=(int)(m&0x3FFFu))
    ROUND32(j6=(int)(m&0x3FFFu))
    ROUND32(j7=(int)(m&0x3FFFu))
    ROUND32(w8=m; j8=(int)(m&0x3FFFu))
    (void)dum;
  }
#undef ROUND32

  if(w8 == INVKEY || (w8>>14) > KNNTH){
    // rare exact fallback (64-bit keys, scalar on lane 0)
    unsigned long long f0=~0ULL,f1=~0ULL,f2=~0ULL,f3=~0ULL,f4=~0ULL,
                       f5=~0ULL,f6=~0ULL,f7=~0ULL,f8=~0ULL;
    if(lane==0){
      for(int d=0; d<HH; d++){
        if(f8 != ~0ULL && (unsigned long long)(d*d) > (f8>>32)) break;
        for(int sgn=0; sgn<2; sgn++){
          if(d==0 && sgn) break;
          int yy = sgn ? qy+d : qy-d;
          if((unsigned)yy >= HH) continue;
          int xlo=0, xhi=WW-1;
          if(f8 != ~0ULL){
            int vv = (int)(f8>>32) - d*d;
            if(vv < 0) continue;
            int hw = isqrt_dev(vv);
            xlo = max(qx-hw,0); xhi = min(qx+hw,WW-1);
          }
          int ss = g_cellStart[yy*NSX + (xlo>>4)];
          int ee = g_cellStart[yy*NSX + (xhi>>4) + 1];
          for(; ss<ee; ss++){
            unsigned long long key = mkkey64(g_packed[ss], qy, qx);
            INS9(f0,f1,f2,f3,f4,f5,f6,f7,f8,key);
          }
        }
      }
    }
    j1=(int)(((unsigned)__shfl_sync(FULLM,(unsigned)f1,0))>>18);
    j2=(int)(((unsigned)__shfl_sync(FULLM,(unsigned)f2,0))>>18);
    j3=(int)(((unsigned)__shfl_sync(FULLM,(unsigned)f3,0))>>18);
    j4=(int)(((unsigned)__shfl_sync(FULLM,(unsigned)f4,0))>>18);
    j5=(int)(((unsigned)__shfl_sync(FULLM,(unsigned)f5,0))>>18);
    j6=(int)(((unsigned)__shfl_sync(FULLM,(unsigned)f6,0))>>18);
    j7=(int)(((unsigned)__shfl_sync(FULLM,(unsigned)f7,0))>>18);
    j8=(int)(((unsigned)__shfl_sync(FULLM,(unsigned)f8,0))>>18);
  }

  // neighbor mean: lane handles neighbor (lane>>2), channels (lane&3)*4..+3
  int ni = lane>>2;
  int j = j1;
  j = (ni==1)?j2:j; j = (ni==2)?j3:j; j = (ni==3)?j4:j;
  j = (ni==4)?j5:j; j = (ni==5)?j6:j; j = (ni==6)?j7:j;
  j = (ni==7)?j8:j;
  int off = __ldg(&grid[2*j])*WW + __ldg(&grid[2*j+1]);
  const float* base = imf + (lane&3)*4*HWIMG + off;
  float4 v;
  v.x = __ldg(base + 0*HWIMG);
  v.y = __ldg(base + 1*HWIMG);
  v.z = __ldg(base + 2*HWIMG);
  v.w = __ldg(base + 3*HWIMG);
#pragma unroll
  for(int o=4;o<=16;o<<=1){
    v.x += __shfl_xor_sync(FULLM, v.x, o);
    v.y += __shfl_xor_sync(FULLM, v.y, o);
    v.z += __shfl_xor_sync(FULLM, v.z, o);
    v.w += __shfl_xor_sync(FULLM, v.w, o);
  }
  if(lane < 4){
    v.x*=0.125f; v.y*=0.125f; v.z*=0.125f; v.w*=0.125f;
    ((float4*)(g_neigh + n*CC))[lane] = v;
  }
}

// ------------------------- K3: deform attn + fuse + final BN (4 thr/point) --
__global__ void __launch_bounds__(NT) k_EG(const int* __restrict__ grid,
    const float* __restrict__ Wfc, const float* __restrict__ gfc, const float* __restrict__ betafc,
    const float* __restrict__ gt,  const float* __restrict__ betat,
    const float* __restrict__ Woff,const float* __restrict__ boff,
    const float* __restrict__ Wattn,const float* __restrict__ battn,
    const float* __restrict__ Wout,const float* __restrict__ bout,
    const float* __restrict__ Wf,  const float* __restrict__ bf,
    const float* __restrict__ gf,  const float* __restrict__ betaf,
    float* __restrict__ out){
  __shared__ float sF[40];
  __shared__ float sWoff[CC*32], sWattn[CC*16], sWout[CC*16], sWf[32*CC];
  __shared__ float sboff[32], sbattn[16], sbout[16], sbf[16];
  __shared__ float sa3[16], sb3[16], su0[16], su1[16], sb2[16], sc[2];
  __shared__ float red[NW][32];
  __shared__ float sP[32], a4[16], b4[16];
  int b=blockIdx.x, t=threadIdx.x;
  int lane=t&31, w=t>>5, r=t&3;
  int gbase = (lane&~3);

  // prefetch per-point data FIRST (hide latency behind smem staging + prologue)
  int n = b*PPB + (t>>2);
  int qyi = __ldg(&grid[2*n]), qxi = __ldg(&grid[2*n+1]);
  float4 pv = __ldg((const float4*)(g_pts + n*CC + 4*r));
  float4 yv = __ldg((const float4*)(g_Y3 + n*CC + 4*r));
  float4 nb = __ldg((const float4*)(g_neigh + n*CC + 4*r));

  if(b==0 && t==0){
    *(volatile int*)&g_bc[0]=0;
    *(volatile int*)&g_bc[1]=0;
    *(volatile int*)&g_bc[2]=0;
  }
  for(int i=t;i<CC*32;i+=NT) sWoff[i]=Woff[i];
  for(int i=t;i<CC*16;i+=NT){ sWattn[i]=Wattn[i]; sWout[i]=Wout[i]; }
  for(int i=t;i<32*CC;i+=NT) sWf[i]=Wf[i];
  if(t<32) sboff[t]=boff[t];
  if(t<16){ sbattn[t]=battn[t]; sbout[t]=bout[t]; sbf[t]=bf[t]; }
  for(int i=w;i<35;i+=NW){
    const float* pp = g_p2 + i*NBB;
    float s = pp[lane]+pp[lane+32]+pp[lane+64]+pp[lane+96];
    s = warpSum(s);
    if(!lane) sF[i]=s;
  }
  if(w==4){
    const float* pp = g_p2 + 35*NBB;
    float m = fmaxf(fmaxf(pp[lane],pp[lane+32]),fmaxf(pp[lane+64],pp[lane+96]));
    m = warpMax(m);
    if(!lane) sF[35]=m;
  } else if(w==5){
    const float* pp = g_p2 + 36*NBB;
    float m = fmaxf(fmaxf(pp[lane],pp[lane+32]),fmaxf(pp[lane+64],pp[lane+96]));
    m = warpMax(m);
    if(!lane) sF[36]=m;
  } else if(w==6){
    const float* pp = g_pA + 32*NBB;
    float s = pp[lane]+pp[lane+32]+pp[lane+64]+pp[lane+96];
    s = warpSum(s);
    if(!lane) sF[37]=s;
  } else if(w==7){
    const float* pp = g_pA + 33*NBB;
    float s = pp[lane]+pp[lane+32]+pp[lane+64]+pp[lane+96];
    s = warpSum(s);
    if(!lane) sF[38]=s;
  }
  __syncthreads();
  if(t<16){
    float m3 = sF[t]*INVN;
    float v3 = sF[16+t]*INVN - m3*m3;
    float is3 = rsqrtf(v3+EPSBN);
    sa3[t] = is3*gt[t];
    sb3[t] = betat[t] - m3*is3*gt[t];
    float mxy = sF[35]; if(mxy==0.f) mxy=1.f;
    float mxx = sF[36]; if(mxx==0.f) mxx=1.f;
    float Syy=sF[32]*INVN, Sxx=sF[33]*INVN, Sxy=sF[34]*INVN;
    float w0 = Wfc[t]/mxy;
    float w1 = Wfc[16+t]/mxx;
    float v2 = w0*w0*Syy + 2.f*w0*w1*Sxy + w1*w1*Sxx;
    float a2 = rsqrtf(v2+EPSBN)*gfc[t];
    su0[t]=w0*a2; su1[t]=w1*a2; sb2[t]=betafc[t];
  }
  if(t==16){ sc[0]=sF[37]*INVN; sc[1]=sF[38]*INVN; }
  __syncthreads();

  float gy=(float)qyi, gx=(float)qxi;
  float ry=gy-sc[0], rx=gx-sc[1];
  float q4[4];
  q4[0]=pv.x+ry*su0[4*r+0]+rx*su1[4*r+0]+sb2[4*r+0];
  q4[1]=pv.y+ry*su0[4*r+1]+rx*su1[4*r+1]+sb2[4*r+1];
  q4[2]=pv.z+ry*su0[4*r+2]+rx*su1[4*r+2]+sb2[4*r+2];
  q4[3]=pv.w+ry*su0[4*r+3]+rx*su1[4*r+3]+sb2[4*r+3];

  // thread r owns head r: 4 logits + 8 offsets
  float lg[4], offy[4], offx[4];
#pragma unroll
  for(int p=0;p<4;p++){
    lg[p]=sbattn[4*r+p];
    offy[p]=sboff[r*8+p*2];
    offx[p]=sboff[r*8+p*2+1];
  }
#pragma unroll
  for(int rr=0;rr<4;rr++){
    float qs[4];
#pragma unroll
    for(int k=0;k<4;k++) qs[k]=__shfl_sync(FULLM, q4[k], gbase+rr);
#pragma unroll
    for(int k=0;k<4;k++){
      int c = 4*rr+k;
#pragma unroll
      for(int p=0;p<4;p++){
        lg[p]  += qs[k]*sWattn[c*16 + 4*r + p];
        offy[p]+= qs[k]*sWoff[c*32 + r*8 + p*2];
        offx[p]+= qs[k]*sWoff[c*32 + r*8 + p*2+1];
      }
    }
  }
  float mx=fmaxf(fmaxf(lg[0],lg[1]),fmaxf(lg[2],lg[3]));
  float e0=expf(lg[0]-mx), e1=expf(lg[1]-mx), e2=expf(lg[2]-mx), e3=expf(lg[3]-mx);
  float inv=1.f/(e0+e1+e2+e3);
  lg[0]=e0*inv; lg[1]=e1*inv; lg[2]=e2*inv; lg[3]=e3*inv;

  float acc4[4]={0.f,0.f,0.f,0.f};
#define CORNER(Yf,Xf,Wgt) do{ \
    float _y=(Yf), _x=(Xf); \
    if(_y>=0.f && _y<=(float)(HH-1) && _x>=0.f && _x<=(float)(WW-1)){ \
      int _i = ((int)_y)*WW + (int)_x; \
      const float4 _v = *(const float4*)(g_val + _i*CC + 4*r); \
      float _w=(Wgt); \
      acc4[0]+=_w*_v.x; acc4[1]+=_w*_v.y; acc4[2]+=_w*_v.z; acc4[3]+=_w*_v.w; \
    } }while(0)
#pragma unroll
  for(int p=0;p<4;p++){
    float ly=gy+offy[p], lx=gx+offx[p];
    float fy=floorf(ly), fx=floorf(lx);
    float wy=ly-fy, wx=lx-fx;
    float ap=lg[p];
    CORNER(fy,     fx,     ap*(1.f-wy)*(1.f-wx));
    CORNER(fy,     fx+1.f, ap*(1.f-wy)*wx);
    CORNER(fy+1.f, fx,     ap*wy*(1.f-wx));
    CORNER(fy+1.f, fx+1.f, ap*wy*wx);
  }
#undef CORNER

  float img4[4];
#pragma unroll
  for(int j=0;j<4;j++) img4[j]=sbout[4*r+j];
#pragma unroll
  for(int rr=0;rr<4;rr++){
    float as[4];
#pragma unroll
    for(int k=0;k<4;k++) as[k]=__shfl_sync(FULLM, acc4[k], gbase+rr);
#pragma unroll
    for(int k=0;k<4;k++)
#pragma unroll
      for(int j=0;j<4;j++) img4[j] += as[k]*sWout[(4*rr+k)*16 + 4*r+j];
  }
  img4[0]+=nb.x; img4[1]+=nb.y; img4[2]+=nb.z; img4[3]+=nb.w;

  float pp4[4];
  pp4[0]=yv.x*sa3[4*r+0]+sb3[4*r+0];
  pp4[1]=yv.y*sa3[4*r+1]+sb3[4*r+1];
  pp4[2]=yv.z*sa3[4*r+2]+sb3[4*r+2];
  pp4[3]=yv.w*sa3[4*r+3]+sb3[4*r+3];

  float y4f[4];
#pragma unroll
  for(int j=0;j<4;j++) y4f[j]=sbf[4*r+j];
#pragma unroll
  for(int rr=0;rr<4;rr++){
    float ps[4], is_[4];
#pragma unroll
    for(int k=0;k<4;k++){
      ps[k] =__shfl_sync(FULLM, pp4[k],  gbase+rr);
      is_[k]=__shfl_sync(FULLM, img4[k], gbase+rr);
    }
#pragma unroll
    for(int k=0;k<4;k++){
      float pvv=fmaxf(ps[k],0.f), iv=fmaxf(is_[k],0.f);
#pragma unroll
      for(int j=0;j<4;j++)
        y4f[j] += pvv*sWf[(4*rr+k)*16 + 4*r+j] + iv*sWf[(16+4*rr+k)*16 + 4*r+j];
    }
  }
  {
    float s1[4], s2[4];
#pragma unroll
    for(int j=0;j<4;j++){ s1[j]=y4f[j]; s2[j]=y4f[j]*y4f[j]; }
#pragma unroll
    for(int o=4;o<32;o<<=1)
#pragma unroll
      for(int j=0;j<4;j++){
        s1[j]+=__shfl_down_sync(FULLM,s1[j],o);
        s2[j]+=__shfl_down_sync(FULLM,s2[j],o);
      }
    if(lane<4)
#pragma unroll
      for(int j=0;j<4;j++){ red[w][4*lane+j]=s1[j]; red[w][16+4*lane+j]=s2[j]; }
  }
  __syncthreads();
  if(t<32){
    float s=0.f;
#pragma unroll
    for(int k=0;k<NW;k++) s += red[k][t];
    g_p3[t*NBB+b]=s;
  }

  gbar(3);

  // ---- final BN + relu (y4f still in registers) ----
  for(int i=w;i<32;i+=NW){
    const float* pp = g_p3 + i*NBB;
    float s = pp[lane]+pp[lane+32]+pp[lane+64]+pp[lane+96];
    s = warpSum(s);
    if(!lane) sP[i]=s;
  }
  __syncthreads();
  if(t<16){
    float m = sP[t]*INVN;
    float vv = sP[16+t]*INVN - m*m;
    float is = rsqrtf(vv+EPSBN);
    a4[t]=is*gf[t];
    b4[t]=betaf[t] - m*is*gf[t];
  }
  __syncthreads();
  float4 ov;
  ov.x = fmaxf(y4f[0]*a4[4*r+0]+b4[4*r+0], 0.f);
  ov.y = fmaxf(y4f[1]*a4[4*r+1]+b4[4*r+1], 0.f);
  ov.z = fmaxf(y4f[2]*a4[4*r+2]+b4[4*r+2], 0.f);
  ov.w = fmaxf(y4f[3]*a4[4*r+3]+b4[4*r+3], 0.f);
  *(float4*)(out + n*CC + 4*r) = ov;
}

// ------------------------- launch ------------------------------------------
extern "C" void kernel_launch(void* const* d_in, const int* in_sizes, int n_in,
                              void* d_out, int out_size){
  const float* pf     = (const float*)d_in[0];
  const float* imf    = (const float*)d_in[1];
  const int*   grid   = (const int*)  d_in[2];
  const float* Wk     = (const float*)d_in[3];
  const float* bk     = (const float*)d_in[4];
  const float* gk     = (const float*)d_in[5];
  const float* betak  = (const float*)d_in[6];
  const float* Wfc    = (const float*)d_in[7];
  /* bfc = d_in[8] cancels analytically */
  const float* gfc    = (const float*)d_in[9];
  const float* betafc = (const float*)d_in[10];
  const float* Wt     = (const float*)d_in[11];
  const float* bt     = (const float*)d_in[12];
  const float* gt     = (const float*)d_in[13];
  const float* betat  = (const float*)d_in[14];
  const float* Woff   = (const float*)d_in[15];
  const float* boff   = (const float*)d_in[16];
  const float* Wattn  = (const float*)d_in[17];
  const float* battn  = (const float*)d_in[18];
  const float* Wval   = (const float*)d_in[19];
  const float* bval   = (const float*)d_in[20];
  const float* Wout   = (const float*)d_in[21];
  const float* bout   = (const float*)d_in[22];
  const float* Wf     = (const float*)d_in[23];
  const float* bf     = (const float*)d_in[24];
  const float* gf     = (const float*)d_in[25];
  const float* betaf  = (const float*)d_in[26];
  float* out = (float*)d_out;

  k_SS <<<NBB+INITB, NT>>>(pf, grid, Wk, bk, gk, betak, Wt, bt, imf, Wval, bval);
  k_knn<<<NPTS/4, 128>>>(grid, imf);
  k_EG <<<NBB, NT>>>(grid, Wfc, gfc, betafc, gt, betat,
                     Woff, boff, Wattn, battn, Wout, bout, Wf, bf,
                     gf, betaf, out);
}